// round 1
// baseline (speedup 1.0000x reference)
#include <cuda_runtime.h>
#include <math.h>
#include <float.h>

#define B_  2
#define L_  2048
#define D_  1024
#define H_  16
#define DH  64
#define BL  (B_*L_)     // 4096
#define E3  (3*D_)      // 3072
#define AST 65          // padded smem stride for attention tiles

// ---- scratch (static device globals; no allocation allowed) ----
__device__ float g_qkv[(size_t)BL * E3];      // 50 MB  raw qkv
__device__ float g_q[(size_t)B_*H_*L_*DH];    // 16 MB  [b,h,l,d]
__device__ float g_k[(size_t)B_*H_*L_*DH];
__device__ float g_v[(size_t)B_*H_*L_*DH];
__device__ float g_ao[(size_t)BL * D_];       // 16 MB  attention output [b,l,h*dh]

// ============================================================
// GEMM: C[M,N] = A[M,K] * Bm[N,K]^T   (row-major A, Bm)
// 128x128 tile, KT=8, 256 threads, 8x8 microtile per thread
// ============================================================
__global__ __launch_bounds__(256) void gemm_nt(const float* __restrict__ A,
                                               const float* __restrict__ Bm,
                                               float* __restrict__ C,
                                               int M, int N, int K) {
    __shared__ float As[8][128];
    __shared__ float Bs[8][128];
    int tid = threadIdx.x;
    int bn = blockIdx.x * 128;
    int bm = blockIdx.y * 128;
    int tx = tid & 15;        // 16 cols of 8
    int ty = tid >> 4;        // 16 rows of 8
    int lr = tid >> 1;        // 0..127 (tile row for loads)
    int lk = (tid & 1) << 2;  // 0 or 4

    const float* Ap = A + (size_t)(bm + lr) * K + lk;
    const float* Bp = Bm + (size_t)(bn + lr) * K + lk;

    float acc[8][8];
#pragma unroll
    for (int i = 0; i < 8; i++)
#pragma unroll
        for (int j = 0; j < 8; j++) acc[i][j] = 0.0f;

    for (int k0 = 0; k0 < K; k0 += 8) {
        float4 av = *(const float4*)(Ap + k0);
        float4 bv = *(const float4*)(Bp + k0);
        __syncthreads();
        As[lk + 0][lr] = av.x; As[lk + 1][lr] = av.y;
        As[lk + 2][lr] = av.z; As[lk + 3][lr] = av.w;
        Bs[lk + 0][lr] = bv.x; Bs[lk + 1][lr] = bv.y;
        Bs[lk + 2][lr] = bv.z; Bs[lk + 3][lr] = bv.w;
        __syncthreads();
#pragma unroll
        for (int kk = 0; kk < 8; kk++) {
            float4 a0 = *(const float4*)&As[kk][ty * 8];
            float4 a1 = *(const float4*)&As[kk][ty * 8 + 4];
            float4 b0 = *(const float4*)&Bs[kk][tx * 8];
            float4 b1 = *(const float4*)&Bs[kk][tx * 8 + 4];
            float a[8] = {a0.x, a0.y, a0.z, a0.w, a1.x, a1.y, a1.z, a1.w};
            float b[8] = {b0.x, b0.y, b0.z, b0.w, b1.x, b1.y, b1.z, b1.w};
#pragma unroll
            for (int i = 0; i < 8; i++)
#pragma unroll
                for (int j = 0; j < 8; j++)
                    acc[i][j] = fmaf(a[i], b[j], acc[i][j]);
        }
    }

#pragma unroll
    for (int i = 0; i < 8; i++) {
        int row = bm + ty * 8 + i;
        float4* cp = (float4*)(C + (size_t)row * N + bn + tx * 8);
        cp[0] = make_float4(acc[i][0], acc[i][1], acc[i][2], acc[i][3]);
        cp[1] = make_float4(acc[i][4], acc[i][5], acc[i][6], acc[i][7]);
    }
}

// ============================================================
// RoPE + split/transpose: g_qkv [BL,3,H,DH] -> g_q/g_k (roped), g_v
// layout out: [(b*H+h)*L + l]*DH + d
// one thread per (even,odd) pair
// ============================================================
__global__ __launch_bounds__(256) void rope_split(const int* __restrict__ pos_ids) {
    int idx = blockIdx.x * blockDim.x + threadIdx.x;   // < BL*3*H*32 = 6291456
    int i = idx & 31;
    int rest = idx >> 5;
    int h = rest & 15;
    int rest2 = rest >> 4;     // bl*3 + s
    int s = rest2 % 3;
    int bl = rest2 / 3;

    const float2 e = *(const float2*)(g_qkv + (size_t)bl * E3 + (s * H_ + h) * DH + 2 * i);

    int b = bl >> 11;          // / L_
    int l = bl & (L_ - 1);
    size_t dst = ((size_t)(b * H_ + h) * L_ + l) * DH + 2 * i;

    if (s == 2) {
        *(float2*)(g_v + dst) = e;
    } else {
        float pos = (float)pos_ids[bl];
        float invf = powf(10000.0f, -(float)i * (1.0f / 32.0f));
        float ang = pos * invf;
        float c, sn;
        sincosf(ang, &sn, &c);
        float2 r;
        r.x = e.x * c - e.y * sn;
        r.y = e.x * sn + e.y * c;
        *(float2*)((s == 0 ? g_q : g_k) + dst) = r;
    }
}

// ============================================================
// Causal flash attention, fp32.
// grid: (L/64, B*H), 128 threads. Each block: 64 queries x full causal K range.
// smem: qs (Q^T [d][m]), ks (K^T [d][n]), vs ([j][c]), ps (P^T [c? -> [j][m]])
// thread (tx,ty): rows r=ty*4+i (4), cols c=tx*8+j (8)
// ============================================================
__global__ __launch_bounds__(128) void attn_kernel() {
    extern __shared__ float sm[];
    float* qs = sm;                // [64][AST]
    float* ks = sm + 64 * AST;     // [64][AST]
    float* vs = sm + 2 * 64 * AST; // [64][AST]
    float* ps = sm + 3 * 64 * AST; // [64][AST]  P stored as ps[col*AST+row]

    int qt = blockIdx.x;
    int bh = blockIdx.y;
    int tid = threadIdx.x;
    int tx = tid & 7;
    int ty = tid >> 3;

    const float* Qb = g_q + ((size_t)bh * L_ + qt * 64) * DH;
#pragma unroll
    for (int it = 0; it < 32; it++) {
        int lin = it * 128 + tid;
        int m = lin >> 6, d = lin & 63;
        qs[d * AST + m] = Qb[m * DH + d];
    }

    float o[4][8];
    float mr[4], lw[4];
#pragma unroll
    for (int i = 0; i < 4; i++) {
        mr[i] = -FLT_MAX; lw[i] = 0.0f;
#pragma unroll
        for (int j = 0; j < 8; j++) o[i][j] = 0.0f;
    }
    __syncthreads();

    for (int jt = 0; jt <= qt; jt++) {
        const float* Kb = g_k + ((size_t)bh * L_ + jt * 64) * DH;
        const float* Vb = g_v + ((size_t)bh * L_ + jt * 64) * DH;
#pragma unroll
        for (int it = 0; it < 32; it++) {
            int lin = it * 128 + tid;
            int n = lin >> 6, d = lin & 63;
            ks[d * AST + n] = Kb[n * DH + d];
            vs[n * AST + d] = Vb[n * DH + d];
        }
        __syncthreads();

        float s[4][8];
#pragma unroll
        for (int i = 0; i < 4; i++)
#pragma unroll
            for (int j = 0; j < 8; j++) s[i][j] = 0.0f;

#pragma unroll 8
        for (int d = 0; d < 64; d++) {
            float a[4], b[8];
#pragma unroll
            for (int i = 0; i < 4; i++) a[i] = qs[d * AST + ty * 4 + i];
#pragma unroll
            for (int j = 0; j < 8; j++) b[j] = ks[d * AST + tx * 8 + j];
#pragma unroll
            for (int i = 0; i < 4; i++)
#pragma unroll
                for (int j = 0; j < 8; j++)
                    s[i][j] = fmaf(a[i], b[j], s[i][j]);
        }

        // scale + causal mask (only diagonal tile is partial)
#pragma unroll
        for (int i = 0; i < 4; i++)
#pragma unroll
            for (int j = 0; j < 8; j++) {
                s[i][j] *= 0.125f;
                if (jt == qt && (tx * 8 + j) > (ty * 4 + i)) s[i][j] = -FLT_MAX;
            }

        // online softmax (row stats shared across the 8-lane tx group)
#pragma unroll
        for (int i = 0; i < 4; i++) {
            float tm = s[i][0];
#pragma unroll
            for (int j = 1; j < 8; j++) tm = fmaxf(tm, s[i][j]);
#pragma unroll
            for (int off = 1; off < 8; off <<= 1)
                tm = fmaxf(tm, __shfl_xor_sync(0xffffffffu, tm, off));
            float mn = fmaxf(mr[i], tm);
            float corr = expf(mr[i] - mn);
            float rs = 0.0f;
#pragma unroll
            for (int j = 0; j < 8; j++) {
                s[i][j] = expf(s[i][j] - mn);
                rs += s[i][j];
            }
#pragma unroll
            for (int off = 1; off < 8; off <<= 1)
                rs += __shfl_xor_sync(0xffffffffu, rs, off);
            lw[i] = lw[i] * corr + rs;
#pragma unroll
            for (int j = 0; j < 8; j++) o[i][j] *= corr;
            mr[i] = mn;
        }

        // write P (transposed: ps[col][row])
#pragma unroll
        for (int i = 0; i < 4; i++)
#pragma unroll
            for (int j = 0; j < 8; j++)
                ps[(tx * 8 + j) * AST + ty * 4 + i] = s[i][j];
        __syncthreads();

        // O += P @ V
#pragma unroll 8
        for (int j = 0; j < 64; j++) {
            float pa[4], vb[8];
#pragma unroll
            for (int i = 0; i < 4; i++) pa[i] = ps[j * AST + ty * 4 + i];
#pragma unroll
            for (int jj = 0; jj < 8; jj++) vb[jj] = vs[j * AST + tx * 8 + jj];
#pragma unroll
            for (int i = 0; i < 4; i++)
#pragma unroll
                for (int jj = 0; jj < 8; jj++)
                    o[i][jj] = fmaf(pa[i], vb[jj], o[i][jj]);
        }
        __syncthreads();
    }

    int b = bh >> 4, h = bh & 15;
#pragma unroll
    for (int i = 0; i < 4; i++) {
        float inv = 1.0f / lw[i];
        int row = qt * 64 + ty * 4 + i;
        float* op = g_ao + ((size_t)(b * L_ + row)) * D_ + h * DH + tx * 8;
        float4 v0 = make_float4(o[i][0] * inv, o[i][1] * inv, o[i][2] * inv, o[i][3] * inv);
        float4 v1 = make_float4(o[i][4] * inv, o[i][5] * inv, o[i][6] * inv, o[i][7] * inv);
        ((float4*)op)[0] = v0;
        ((float4*)op)[1] = v1;
    }
}

// ============================================================
extern "C" void kernel_launch(void* const* d_in, const int* in_sizes, int n_in,
                              void* d_out, int out_size) {
    const float* x    = (const float*)d_in[0];
    const float* Wqkv = (const float*)d_in[1];
    const float* Wout = (const float*)d_in[2];
    const int*   pos  = (const int*)d_in[3];
    // d_in[4] = attn_mask_2d (causal tril), encoded by the causal loop bounds
    float* out = (float*)d_out;

    float *p_qkv, *p_ao;
    cudaGetSymbolAddress((void**)&p_qkv, g_qkv);
    cudaGetSymbolAddress((void**)&p_ao, g_ao);

    const int attn_smem = 4 * 64 * AST * sizeof(float);  // 66,560 B
    cudaFuncSetAttribute(attn_kernel, cudaFuncAttributeMaxDynamicSharedMemorySize, attn_smem);

    // 1) qkv = x @ W_qkv^T
    gemm_nt<<<dim3(E3 / 128, BL / 128), 256>>>(x, Wqkv, p_qkv, BL, E3, D_);
    // 2) rope + split into head-major q,k,v
    rope_split<<<(BL * E3 / 2) / 256, 256>>>(pos);
    // 3) causal attention -> g_ao [b,l,h*dh]
    attn_kernel<<<dim3(L_ / 64, B_ * H_), 128, attn_smem>>>();
    // 4) out = g_ao @ W_out^T
    gemm_nt<<<dim3(D_ / 128, BL / 128), 256>>>(p_ao, Wout, out, BL, D_, D_);
}

// round 7
// speedup vs baseline: 1.5672x; 1.5672x over previous
#include <cuda_runtime.h>
#include <math.h>
#include <float.h>
#include <cstdint>

#define B_  2
#define L_  2048
#define D_  1024
#define H_  16
#define DH  64
#define BL  (B_*L_)     // 4096
#define E3  (3*D_)      // 3072
#define AST 65          // padded smem stride for attention tiles

// ---- scratch (static device globals; no allocation allowed) ----
__device__ float g_qkv[(size_t)BL * E3];      // 50 MB  raw qkv
__device__ float g_q[(size_t)B_*H_*L_*DH];    // 16 MB  [b,h,l,d]
__device__ float g_k[(size_t)B_*H_*L_*DH];
__device__ float g_v[(size_t)B_*H_*L_*DH];
__device__ float g_ao[(size_t)BL * D_];       // 16 MB  attention output [b,l,h*dh]

__device__ __forceinline__ uint32_t f2tf32(float x) {
    uint32_t r;
    asm("cvt.rna.tf32.f32 %0, %1;" : "=r"(r) : "f"(x));
    return r;
}

__device__ __forceinline__ void mma_tf32(float* d, const uint32_t* a, const uint32_t* b) {
    asm volatile(
        "mma.sync.aligned.m16n8k8.row.col.f32.tf32.tf32.f32 "
        "{%0,%1,%2,%3}, {%4,%5,%6,%7}, {%8,%9}, {%0,%1,%2,%3};"
        : "+f"(d[0]), "+f"(d[1]), "+f"(d[2]), "+f"(d[3])
        : "r"(a[0]), "r"(a[1]), "r"(a[2]), "r"(a[3]), "r"(b[0]), "r"(b[1]));
}

// ============================================================
// mma.sync tf32 GEMM: C[M,N] = A[M,K] * Bm[N,K]^T  (row-major A, Bm)
// 128x128 CTA tile, KT=16 double-buffered, 256 threads (8 warps 2x4).
// smem stride 20 words: conflict-free for frag loads ((20g+tg) mod 32 distinct)
// ============================================================
#define KT 16
#define SST 20

__global__ __launch_bounds__(256) void gemm_mma(const float* __restrict__ A,
                                                const float* __restrict__ Bm,
                                                float* __restrict__ C,
                                                int N, int K) {
    __shared__ uint32_t As[2][128][SST];
    __shared__ uint32_t Bs[2][128][SST];

    int tid = threadIdx.x;
    int wid = tid >> 5, lane = tid & 31;
    int g = lane >> 2, tg = lane & 3;
    int wm = (wid & 1) * 64;          // warp m offset in tile
    int wn = (wid >> 1) * 32;         // warp n offset in tile
    int bn = blockIdx.x * 128;
    int bm = blockIdx.y * 128;
    const int NT = K / KT;

    int lr = tid >> 1;                // 0..127 load row
    int lc = (tid & 1) * 8;           // col base (0 or 8)

    const float* Ap = A  + (size_t)(bm + lr) * K + lc;
    const float* Bp = Bm + (size_t)(bn + lr) * K + lc;

    float4 ra0, ra1, rb0, rb1;
#define LOADG(k0) do { \
        ra0 = *(const float4*)(Ap + (k0));     ra1 = *(const float4*)(Ap + (k0) + 4); \
        rb0 = *(const float4*)(Bp + (k0));     rb1 = *(const float4*)(Bp + (k0) + 4); \
    } while (0)
#define STS(s) do { \
        As[s][lr][lc + 0] = f2tf32(ra0.x); As[s][lr][lc + 1] = f2tf32(ra0.y); \
        As[s][lr][lc + 2] = f2tf32(ra0.z); As[s][lr][lc + 3] = f2tf32(ra0.w); \
        As[s][lr][lc + 4] = f2tf32(ra1.x); As[s][lr][lc + 5] = f2tf32(ra1.y); \
        As[s][lr][lc + 6] = f2tf32(ra1.z); As[s][lr][lc + 7] = f2tf32(ra1.w); \
        Bs[s][lr][lc + 0] = f2tf32(rb0.x); Bs[s][lr][lc + 1] = f2tf32(rb0.y); \
        Bs[s][lr][lc + 2] = f2tf32(rb0.z); Bs[s][lr][lc + 3] = f2tf32(rb0.w); \
        Bs[s][lr][lc + 4] = f2tf32(rb1.x); Bs[s][lr][lc + 5] = f2tf32(rb1.y); \
        Bs[s][lr][lc + 6] = f2tf32(rb1.z); Bs[s][lr][lc + 7] = f2tf32(rb1.w); \
    } while (0)

    float acc[4][4][4];
#pragma unroll
    for (int mt = 0; mt < 4; mt++)
#pragma unroll
        for (int nt = 0; nt < 4; nt++)
#pragma unroll
            for (int q = 0; q < 4; q++) acc[mt][nt][q] = 0.0f;

    LOADG(0);
    STS(0);
    __syncthreads();

    for (int kt = 0; kt < NT; kt++) {
        if (kt + 1 < NT) LOADG((kt + 1) * KT);
        int s = kt & 1;
#pragma unroll
        for (int kk = 0; kk < KT; kk += 8) {
            uint32_t af[4][4], bf[4][2];
#pragma unroll
            for (int mt = 0; mt < 4; mt++) {
                int r0 = wm + mt * 16 + g;
                af[mt][0] = As[s][r0][kk + tg];
                af[mt][1] = As[s][r0 + 8][kk + tg];
                af[mt][2] = As[s][r0][kk + tg + 4];
                af[mt][3] = As[s][r0 + 8][kk + tg + 4];
            }
#pragma unroll
            for (int nt = 0; nt < 4; nt++) {
                int c0 = wn + nt * 8 + g;
                bf[nt][0] = Bs[s][c0][kk + tg];
                bf[nt][1] = Bs[s][c0][kk + tg + 4];
            }
#pragma unroll
            for (int mt = 0; mt < 4; mt++)
#pragma unroll
                for (int nt = 0; nt < 4; nt++)
                    mma_tf32(acc[mt][nt], af[mt], bf[nt]);
        }
        if (kt + 1 < NT) STS((kt + 1) & 1);
        __syncthreads();
    }

#pragma unroll
    for (int mt = 0; mt < 4; mt++) {
        int row = bm + wm + mt * 16 + g;
#pragma unroll
        for (int nt = 0; nt < 4; nt++) {
            int col = bn + wn + nt * 8 + 2 * tg;
            *(float2*)(C + (size_t)row * N + col)       = make_float2(acc[mt][nt][0], acc[mt][nt][1]);
            *(float2*)(C + (size_t)(row + 8) * N + col) = make_float2(acc[mt][nt][2], acc[mt][nt][3]);
        }
    }
#undef LOADG
#undef STS
}

// ============================================================
// RoPE + split/transpose: g_qkv [BL,3,H,DH] -> g_q/g_k (roped), g_v
// ============================================================
__global__ __launch_bounds__(256) void rope_split(const int* __restrict__ pos_ids) {
    int idx = blockIdx.x * blockDim.x + threadIdx.x;
    int i = idx & 31;
    int rest = idx >> 5;
    int h = rest & 15;
    int rest2 = rest >> 4;
    int s = rest2 % 3;
    int bl = rest2 / 3;

    const float2 e = *(const float2*)(g_qkv + (size_t)bl * E3 + (s * H_ + h) * DH + 2 * i);

    int b = bl >> 11;
    int l = bl & (L_ - 1);
    size_t dst = ((size_t)(b * H_ + h) * L_ + l) * DH + 2 * i;

    if (s == 2) {
        *(float2*)(g_v + dst) = e;
    } else {
        float pos = (float)pos_ids[bl];
        float invf = powf(10000.0f, -(float)i * (1.0f / 32.0f));
        float ang = pos * invf;
        float cs, sn;
        sincosf(ang, &sn, &cs);
        float2 r;
        r.x = e.x * cs - e.y * sn;
        r.y = e.x * sn + e.y * cs;
        *(float2*)((s == 0 ? g_q : g_k) + dst) = r;
    }
}

// ============================================================
// Causal flash attention, fp32 SIMT (unchanged — next round's target)
// ============================================================
__global__ __launch_bounds__(128) void attn_kernel() {
    extern __shared__ float sm[];
    float* qs = sm;
    float* ks = sm + 64 * AST;
    float* vs = sm + 2 * 64 * AST;
    float* ps = sm + 3 * 64 * AST;

    int qt = blockIdx.x;
    int bh = blockIdx.y;
    int tid = threadIdx.x;
    int tx = tid & 7;
    int ty = tid >> 3;

    const float* Qb = g_q + ((size_t)bh * L_ + qt * 64) * DH;
#pragma unroll
    for (int it = 0; it < 32; it++) {
        int lin = it * 128 + tid;
        int m = lin >> 6, d = lin & 63;
        qs[d * AST + m] = Qb[m * DH + d];
    }

    float o[4][8];
    float mr[4], lw[4];
#pragma unroll
    for (int i = 0; i < 4; i++) {
        mr[i] = -FLT_MAX; lw[i] = 0.0f;
#pragma unroll
        for (int j = 0; j < 8; j++) o[i][j] = 0.0f;
    }
    __syncthreads();

    for (int jt = 0; jt <= qt; jt++) {
        const float* Kb = g_k + ((size_t)bh * L_ + jt * 64) * DH;
        const float* Vb = g_v + ((size_t)bh * L_ + jt * 64) * DH;
#pragma unroll
        for (int it = 0; it < 32; it++) {
            int lin = it * 128 + tid;
            int n = lin >> 6, d = lin & 63;
            ks[d * AST + n] = Kb[n * DH + d];
            vs[n * AST + d] = Vb[n * DH + d];
        }
        __syncthreads();

        float s[4][8];
#pragma unroll
        for (int i = 0; i < 4; i++)
#pragma unroll
            for (int j = 0; j < 8; j++) s[i][j] = 0.0f;

#pragma unroll 8
        for (int d = 0; d < 64; d++) {
            float a[4], b[8];
#pragma unroll
            for (int i = 0; i < 4; i++) a[i] = qs[d * AST + ty * 4 + i];
#pragma unroll
            for (int j = 0; j < 8; j++) b[j] = ks[d * AST + tx * 8 + j];
#pragma unroll
            for (int i = 0; i < 4; i++)
#pragma unroll
                for (int j = 0; j < 8; j++)
                    s[i][j] = fmaf(a[i], b[j], s[i][j]);
        }

#pragma unroll
        for (int i = 0; i < 4; i++)
#pragma unroll
            for (int j = 0; j < 8; j++) {
                s[i][j] *= 0.125f;
                if (jt == qt && (tx * 8 + j) > (ty * 4 + i)) s[i][j] = -FLT_MAX;
            }

#pragma unroll
        for (int i = 0; i < 4; i++) {
            float tm = s[i][0];
#pragma unroll
            for (int j = 1; j < 8; j++) tm = fmaxf(tm, s[i][j]);
#pragma unroll
            for (int off = 1; off < 8; off <<= 1)
                tm = fmaxf(tm, __shfl_xor_sync(0xffffffffu, tm, off));
            float mn = fmaxf(mr[i], tm);
            float corr = expf(mr[i] - mn);
            float rs = 0.0f;
#pragma unroll
            for (int j = 0; j < 8; j++) {
                s[i][j] = expf(s[i][j] - mn);
                rs += s[i][j];
            }
#pragma unroll
            for (int off = 1; off < 8; off <<= 1)
                rs += __shfl_xor_sync(0xffffffffu, rs, off);
            lw[i] = lw[i] * corr + rs;
#pragma unroll
            for (int j = 0; j < 8; j++) o[i][j] *= corr;
            mr[i] = mn;
        }

#pragma unroll
        for (int i = 0; i < 4; i++)
#pragma unroll
            for (int j = 0; j < 8; j++)
                ps[(tx * 8 + j) * AST + ty * 4 + i] = s[i][j];
        __syncthreads();

#pragma unroll 8
        for (int j = 0; j < 64; j++) {
            float pa[4], vb[8];
#pragma unroll
            for (int i = 0; i < 4; i++) pa[i] = ps[j * AST + ty * 4 + i];
#pragma unroll
            for (int jj = 0; jj < 8; jj++) vb[jj] = vs[j * AST + tx * 8 + jj];
#pragma unroll
            for (int i = 0; i < 4; i++)
#pragma unroll
                for (int jj = 0; jj < 8; jj++)
                    o[i][jj] = fmaf(pa[i], vb[jj], o[i][jj]);
        }
        __syncthreads();
    }

    int b = bh >> 4, h = bh & 15;
#pragma unroll
    for (int i = 0; i < 4; i++) {
        float inv = 1.0f / lw[i];
        int row = qt * 64 + ty * 4 + i;
        float* op = g_ao + ((size_t)(b * L_ + row)) * D_ + h * DH + tx * 8;
        float4 v0 = make_float4(o[i][0] * inv, o[i][1] * inv, o[i][2] * inv, o[i][3] * inv);
        float4 v1 = make_float4(o[i][4] * inv, o[i][5] * inv, o[i][6] * inv, o[i][7] * inv);
        ((float4*)op)[0] = v0;
        ((float4*)op)[1] = v1;
    }
}

// ============================================================
extern "C" void kernel_launch(void* const* d_in, const int* in_sizes, int n_in,
                              void* d_out, int out_size) {
    const float* x    = (const float*)d_in[0];
    const float* Wqkv = (const float*)d_in[1];
    const float* Wout = (const float*)d_in[2];
    const int*   pos  = (const int*)d_in[3];
    float* out = (float*)d_out;

    float *p_qkv, *p_ao;
    cudaGetSymbolAddress((void**)&p_qkv, g_qkv);
    cudaGetSymbolAddress((void**)&p_ao, g_ao);

    const int attn_smem = 4 * 64 * AST * sizeof(float);
    cudaFuncSetAttribute(attn_kernel, cudaFuncAttributeMaxDynamicSharedMemorySize, attn_smem);

    // 1) qkv = x @ W_qkv^T   (mma.sync tf32)
    gemm_mma<<<dim3(E3 / 128, BL / 128), 256>>>(x, Wqkv, p_qkv, E3, D_);
    // 2) rope + split into head-major q,k,v
    rope_split<<<(BL * E3 / 2) / 256, 256>>>(pos);
    // 3) causal attention -> g_ao [b,l,h*dh]
    attn_kernel<<<dim3(L_ / 64, B_ * H_), 128, attn_smem>>>();
    // 4) out = g_ao @ W_out^T  (mma.sync tf32)
    gemm_mma<<<dim3(D_ / 128, BL / 128), 256>>>(p_ao, Wout, out, D_, D_);
}

// round 8
// speedup vs baseline: 1.6262x; 1.0376x over previous
#include <cuda_runtime.h>
#include <math.h>
#include <float.h>
#include <cstdint>

#define B_  2
#define L_  2048
#define D_  1024
#define H_  16
#define DH  64
#define BL  (B_*L_)     // 4096
#define E3  (3*D_)      // 3072

// ---- scratch (static device globals; no allocation allowed) ----
__device__ float g_qkv[(size_t)BL * E3];      // 50 MB  raw qkv
__device__ float g_q[(size_t)B_*H_*L_*DH];    // 16 MB  [b,h,l,d]
__device__ float g_k[(size_t)B_*H_*L_*DH];
__device__ float g_v[(size_t)B_*H_*L_*DH];
__device__ float g_ao[(size_t)BL * D_];       // 16 MB  attention output [b,l,h*dh]

__device__ __forceinline__ uint32_t f2tf32(float x) {
    uint32_t r;
    asm("cvt.rna.tf32.f32 %0, %1;" : "=r"(r) : "f"(x));
    return r;
}

__device__ __forceinline__ void mma_tf32(float* d, const uint32_t* a, const uint32_t* b) {
    asm volatile(
        "mma.sync.aligned.m16n8k8.row.col.f32.tf32.tf32.f32 "
        "{%0,%1,%2,%3}, {%4,%5,%6,%7}, {%8,%9}, {%0,%1,%2,%3};"
        : "+f"(d[0]), "+f"(d[1]), "+f"(d[2]), "+f"(d[3])
        : "r"(a[0]), "r"(a[1]), "r"(a[2]), "r"(a[3]), "r"(b[0]), "r"(b[1]));
}

// ============================================================
// mma.sync tf32 GEMM: C[M,N] = A[M,K] * Bm[N,K]^T  (row-major A, Bm)
// ============================================================
#define KT 16
#define SST 20

__global__ __launch_bounds__(256) void gemm_mma(const float* __restrict__ A,
                                                const float* __restrict__ Bm,
                                                float* __restrict__ C,
                                                int N, int K) {
    __shared__ uint32_t As[2][128][SST];
    __shared__ uint32_t Bs[2][128][SST];

    int tid = threadIdx.x;
    int wid = tid >> 5, lane = tid & 31;
    int g = lane >> 2, tg = lane & 3;
    int wm = (wid & 1) * 64;
    int wn = (wid >> 1) * 32;
    int bn = blockIdx.x * 128;
    int bm = blockIdx.y * 128;
    const int NT = K / KT;

    int lr = tid >> 1;
    int lc = (tid & 1) * 8;

    const float* Ap = A  + (size_t)(bm + lr) * K + lc;
    const float* Bp = Bm + (size_t)(bn + lr) * K + lc;

    float4 ra0, ra1, rb0, rb1;
#define LOADG(k0) do { \
        ra0 = *(const float4*)(Ap + (k0));     ra1 = *(const float4*)(Ap + (k0) + 4); \
        rb0 = *(const float4*)(Bp + (k0));     rb1 = *(const float4*)(Bp + (k0) + 4); \
    } while (0)
#define STS(s) do { \
        As[s][lr][lc + 0] = f2tf32(ra0.x); As[s][lr][lc + 1] = f2tf32(ra0.y); \
        As[s][lr][lc + 2] = f2tf32(ra0.z); As[s][lr][lc + 3] = f2tf32(ra0.w); \
        As[s][lr][lc + 4] = f2tf32(ra1.x); As[s][lr][lc + 5] = f2tf32(ra1.y); \
        As[s][lr][lc + 6] = f2tf32(ra1.z); As[s][lr][lc + 7] = f2tf32(ra1.w); \
        Bs[s][lr][lc + 0] = f2tf32(rb0.x); Bs[s][lr][lc + 1] = f2tf32(rb0.y); \
        Bs[s][lr][lc + 2] = f2tf32(rb0.z); Bs[s][lr][lc + 3] = f2tf32(rb0.w); \
        Bs[s][lr][lc + 4] = f2tf32(rb1.x); Bs[s][lr][lc + 5] = f2tf32(rb1.y); \
        Bs[s][lr][lc + 6] = f2tf32(rb1.z); Bs[s][lr][lc + 7] = f2tf32(rb1.w); \
    } while (0)

    float acc[4][4][4];
#pragma unroll
    for (int mt = 0; mt < 4; mt++)
#pragma unroll
        for (int nt = 0; nt < 4; nt++)
#pragma unroll
            for (int q = 0; q < 4; q++) acc[mt][nt][q] = 0.0f;

    LOADG(0);
    STS(0);
    __syncthreads();

    for (int kt = 0; kt < NT; kt++) {
        if (kt + 1 < NT) LOADG((kt + 1) * KT);
        int s = kt & 1;
#pragma unroll
        for (int kk = 0; kk < KT; kk += 8) {
            uint32_t af[4][4], bf[4][2];
#pragma unroll
            for (int mt = 0; mt < 4; mt++) {
                int r0 = wm + mt * 16 + g;
                af[mt][0] = As[s][r0][kk + tg];
                af[mt][1] = As[s][r0 + 8][kk + tg];
                af[mt][2] = As[s][r0][kk + tg + 4];
                af[mt][3] = As[s][r0 + 8][kk + tg + 4];
            }
#pragma unroll
            for (int nt = 0; nt < 4; nt++) {
                int c0 = wn + nt * 8 + g;
                bf[nt][0] = Bs[s][c0][kk + tg];
                bf[nt][1] = Bs[s][c0][kk + tg + 4];
            }
#pragma unroll
            for (int mt = 0; mt < 4; mt++)
#pragma unroll
                for (int nt = 0; nt < 4; nt++)
                    mma_tf32(acc[mt][nt], af[mt], bf[nt]);
        }
        if (kt + 1 < NT) STS((kt + 1) & 1);
        __syncthreads();
    }

#pragma unroll
    for (int mt = 0; mt < 4; mt++) {
        int row = bm + wm + mt * 16 + g;
#pragma unroll
        for (int nt = 0; nt < 4; nt++) {
            int col = bn + wn + nt * 8 + 2 * tg;
            *(float2*)(C + (size_t)row * N + col)       = make_float2(acc[mt][nt][0], acc[mt][nt][1]);
            *(float2*)(C + (size_t)(row + 8) * N + col) = make_float2(acc[mt][nt][2], acc[mt][nt][3]);
        }
    }
#undef LOADG
#undef STS
}

// ============================================================
// RoPE + split/transpose
// ============================================================
__global__ __launch_bounds__(256) void rope_split(const int* __restrict__ pos_ids) {
    int idx = blockIdx.x * blockDim.x + threadIdx.x;
    int i = idx & 31;
    int rest = idx >> 5;
    int h = rest & 15;
    int rest2 = rest >> 4;
    int s = rest2 % 3;
    int bl = rest2 / 3;

    const float2 e = *(const float2*)(g_qkv + (size_t)bl * E3 + (s * H_ + h) * DH + 2 * i);

    int b = bl >> 11;
    int l = bl & (L_ - 1);
    size_t dst = ((size_t)(b * H_ + h) * L_ + l) * DH + 2 * i;

    if (s == 2) {
        *(float2*)(g_v + dst) = e;
    } else {
        float pos = (float)pos_ids[bl];
        float invf = powf(10000.0f, -(float)i * (1.0f / 32.0f));
        float ang = pos * invf;
        float cs, sn;
        sincosf(ang, &sn, &cs);
        float2 r;
        r.x = e.x * cs - e.y * sn;
        r.y = e.x * sn + e.y * cs;
        *(float2*)((s == 0 ? g_q : g_k) + dst) = r;
    }
}

// ============================================================
// Tensor-core causal flash attention (tf32 mma, 3xTF32 for QK^T).
// grid (L/64, B*H), 128 threads = 4 warps x 16 query rows.
// smem: Q,K hi/lo interleaved [64][QKS] (QKS=136, /2 elems per row, x2 words),
//       V tf32 [64][VST=72], P tf32 [64][PST=68]
// ============================================================
#define QKS 136
#define VST 72
#define PST 68
#define OQ  0
#define OK_ (64*QKS)
#define OV  (2*64*QKS)
#define OP  (2*64*QKS + 64*VST)
#define ATT_SMEM ((2*64*QKS + 64*VST + 64*PST) * 4)   // 105472 B

__global__ __launch_bounds__(128, 2) void attn_tc() {
    extern __shared__ float sm[];
    float* qhl = sm + OQ;
    float* khl = sm + OK_;
    float* vv  = sm + OV;
    float* pp  = sm + OP;

    int qt = gridDim.x - 1 - blockIdx.x;   // heavy tiles first
    int bh = blockIdx.y;
    int tid = threadIdx.x;
    int wid = tid >> 5, lane = tid & 31;
    int g = lane >> 2, tg = lane & 3;
    int rowb = wid * 16;

    const float* Qb = g_q + ((size_t)bh * L_ + qt * 64) * DH;

    // Q: scale by 1/8, hi/lo split, interleaved
#pragma unroll
    for (int it = 0; it < 8; it++) {
        int lin = it * 128 + tid;
        int r = lin >> 4, c = (lin & 15) * 4;
        float4 v = *(const float4*)(Qb + r * DH + c);
        float vals[4] = {v.x * 0.125f, v.y * 0.125f, v.z * 0.125f, v.w * 0.125f};
#pragma unroll
        for (int j = 0; j < 4; j++) {
            float hi = __uint_as_float(f2tf32(vals[j]));
            float lo = __uint_as_float(f2tf32(vals[j] - hi));
            *(float2*)(qhl + r * QKS + (c + j) * 2) = make_float2(hi, lo);
        }
    }

    float o[8][4];
#pragma unroll
    for (int nt = 0; nt < 8; nt++)
#pragma unroll
        for (int q = 0; q < 4; q++) o[nt][q] = 0.0f;
    float mr0 = -1e30f, mr1 = -1e30f, lw0 = 0.0f, lw1 = 0.0f;

    for (int jt = 0; jt <= qt; jt++) {
        __syncthreads();   // previous tile fully consumed
        const float* Kb = g_k + ((size_t)bh * L_ + jt * 64) * DH;
        const float* Vb = g_v + ((size_t)bh * L_ + jt * 64) * DH;
#pragma unroll
        for (int it = 0; it < 8; it++) {
            int lin = it * 128 + tid;
            int r = lin >> 4, c = (lin & 15) * 4;
            float4 kv = *(const float4*)(Kb + r * DH + c);
            float kvals[4] = {kv.x, kv.y, kv.z, kv.w};
#pragma unroll
            for (int j = 0; j < 4; j++) {
                float hi = __uint_as_float(f2tf32(kvals[j]));
                float lo = __uint_as_float(f2tf32(kvals[j] - hi));
                *(float2*)(khl + r * QKS + (c + j) * 2) = make_float2(hi, lo);
            }
            float4 vvv = *(const float4*)(Vb + r * DH + c);
            *(float4*)(vv + r * VST + c) = make_float4(
                __uint_as_float(f2tf32(vvv.x)), __uint_as_float(f2tf32(vvv.y)),
                __uint_as_float(f2tf32(vvv.z)), __uint_as_float(f2tf32(vvv.w)));
        }
        __syncthreads();

        // ---- S = Q K^T (3xTF32) ----
        float s[8][4];
#pragma unroll
        for (int nt = 0; nt < 8; nt++)
#pragma unroll
            for (int q = 0; q < 4; q++) s[nt][q] = 0.0f;

#pragma unroll
        for (int kk = 0; kk < 64; kk += 8) {
            uint32_t ah[4], al[4];
            float2 t;
            t = *(const float2*)(qhl + (rowb + g) * QKS + (kk + tg) * 2);
            ah[0] = __float_as_uint(t.x); al[0] = __float_as_uint(t.y);
            t = *(const float2*)(qhl + (rowb + 8 + g) * QKS + (kk + tg) * 2);
            ah[1] = __float_as_uint(t.x); al[1] = __float_as_uint(t.y);
            t = *(const float2*)(qhl + (rowb + g) * QKS + (kk + tg + 4) * 2);
            ah[2] = __float_as_uint(t.x); al[2] = __float_as_uint(t.y);
            t = *(const float2*)(qhl + (rowb + 8 + g) * QKS + (kk + tg + 4) * 2);
            ah[3] = __float_as_uint(t.x); al[3] = __float_as_uint(t.y);
#pragma unroll
            for (int nt = 0; nt < 8; nt++) {
                float2 b0 = *(const float2*)(khl + (nt * 8 + g) * QKS + (kk + tg) * 2);
                float2 b1 = *(const float2*)(khl + (nt * 8 + g) * QKS + (kk + tg + 4) * 2);
                uint32_t bhv[2] = {__float_as_uint(b0.x), __float_as_uint(b1.x)};
                uint32_t blv[2] = {__float_as_uint(b0.y), __float_as_uint(b1.y)};
                mma_tf32(s[nt], ah, bhv);
                mma_tf32(s[nt], al, bhv);
                mma_tf32(s[nt], ah, blv);
            }
        }

        // causal mask (diag tile only)
        if (jt == qt) {
            int r0 = rowb + g, r1 = rowb + 8 + g;
#pragma unroll
            for (int nt = 0; nt < 8; nt++) {
                int c0 = nt * 8 + 2 * tg;
                if (c0     > r0) s[nt][0] = -1e30f;
                if (c0 + 1 > r0) s[nt][1] = -1e30f;
                if (c0     > r1) s[nt][2] = -1e30f;
                if (c0 + 1 > r1) s[nt][3] = -1e30f;
            }
        }

        // ---- online softmax (rows g / g+8 within warp) ----
        float mx0 = -1e30f, mx1 = -1e30f;
#pragma unroll
        for (int nt = 0; nt < 8; nt++) {
            mx0 = fmaxf(mx0, fmaxf(s[nt][0], s[nt][1]));
            mx1 = fmaxf(mx1, fmaxf(s[nt][2], s[nt][3]));
        }
        mx0 = fmaxf(mx0, __shfl_xor_sync(0xffffffffu, mx0, 1));
        mx0 = fmaxf(mx0, __shfl_xor_sync(0xffffffffu, mx0, 2));
        mx1 = fmaxf(mx1, __shfl_xor_sync(0xffffffffu, mx1, 1));
        mx1 = fmaxf(mx1, __shfl_xor_sync(0xffffffffu, mx1, 2));
        float mn0 = fmaxf(mr0, mx0), mn1 = fmaxf(mr1, mx1);
        float cr0 = __expf(mr0 - mn0), cr1 = __expf(mr1 - mn1);
        float sum0 = 0.0f, sum1 = 0.0f;
#pragma unroll
        for (int nt = 0; nt < 8; nt++) {
            s[nt][0] = __expf(s[nt][0] - mn0);
            s[nt][1] = __expf(s[nt][1] - mn0);
            s[nt][2] = __expf(s[nt][2] - mn1);
            s[nt][3] = __expf(s[nt][3] - mn1);
            sum0 += s[nt][0] + s[nt][1];
            sum1 += s[nt][2] + s[nt][3];
        }
        sum0 += __shfl_xor_sync(0xffffffffu, sum0, 1);
        sum0 += __shfl_xor_sync(0xffffffffu, sum0, 2);
        sum1 += __shfl_xor_sync(0xffffffffu, sum1, 1);
        sum1 += __shfl_xor_sync(0xffffffffu, sum1, 2);
        lw0 = lw0 * cr0 + sum0;
        lw1 = lw1 * cr1 + sum1;
        mr0 = mn0; mr1 = mn1;
#pragma unroll
        for (int nt = 0; nt < 8; nt++) {
            o[nt][0] *= cr0; o[nt][1] *= cr0;
            o[nt][2] *= cr1; o[nt][3] *= cr1;
        }

        // write P (tf32) — per-warp-private rows of pp
#pragma unroll
        for (int nt = 0; nt < 8; nt++) {
            int c0 = nt * 8 + 2 * tg;
            *(float2*)(pp + (rowb + g) * PST + c0) = make_float2(
                __uint_as_float(f2tf32(s[nt][0])), __uint_as_float(f2tf32(s[nt][1])));
            *(float2*)(pp + (rowb + 8 + g) * PST + c0) = make_float2(
                __uint_as_float(f2tf32(s[nt][2])), __uint_as_float(f2tf32(s[nt][3])));
        }
        __syncwarp();

        // ---- O += P V ----
#pragma unroll
        for (int kk = 0; kk < 64; kk += 8) {
            uint32_t af[4];
            af[0] = __float_as_uint(pp[(rowb + g) * PST + kk + tg]);
            af[1] = __float_as_uint(pp[(rowb + 8 + g) * PST + kk + tg]);
            af[2] = __float_as_uint(pp[(rowb + g) * PST + kk + tg + 4]);
            af[3] = __float_as_uint(pp[(rowb + 8 + g) * PST + kk + tg + 4]);
#pragma unroll
            for (int nt = 0; nt < 8; nt++) {
                uint32_t bf[2] = {
                    __float_as_uint(vv[(kk + tg) * VST + nt * 8 + g]),
                    __float_as_uint(vv[(kk + tg + 4) * VST + nt * 8 + g])};
                mma_tf32(o[nt], af, bf);
            }
        }
    }

    // epilogue
    float i0 = 1.0f / lw0, i1 = 1.0f / lw1;
    int b = bh >> 4, h = bh & 15;
    int r0 = qt * 64 + rowb + g, r1 = r0 + 8;
#pragma unroll
    for (int nt = 0; nt < 8; nt++) {
        int col = h * DH + nt * 8 + 2 * tg;
        *(float2*)(g_ao + (size_t)(b * L_ + r0) * D_ + col) =
            make_float2(o[nt][0] * i0, o[nt][1] * i0);
        *(float2*)(g_ao + (size_t)(b * L_ + r1) * D_ + col) =
            make_float2(o[nt][2] * i1, o[nt][3] * i1);
    }
}

// ============================================================
extern "C" void kernel_launch(void* const* d_in, const int* in_sizes, int n_in,
                              void* d_out, int out_size) {
    const float* x    = (const float*)d_in[0];
    const float* Wqkv = (const float*)d_in[1];
    const float* Wout = (const float*)d_in[2];
    const int*   pos  = (const int*)d_in[3];
    float* out = (float*)d_out;

    float *p_qkv, *p_ao;
    cudaGetSymbolAddress((void**)&p_qkv, g_qkv);
    cudaGetSymbolAddress((void**)&p_ao, g_ao);

    cudaFuncSetAttribute(attn_tc, cudaFuncAttributeMaxDynamicSharedMemorySize, ATT_SMEM);

    // 1) qkv = x @ W_qkv^T   (mma.sync tf32)
    gemm_mma<<<dim3(E3 / 128, BL / 128), 256>>>(x, Wqkv, p_qkv, E3, D_);
    // 2) rope + split into head-major q,k,v
    rope_split<<<(BL * E3 / 2) / 256, 256>>>(pos);
    // 3) tensor-core causal flash attention -> g_ao
    attn_tc<<<dim3(L_ / 64, B_ * H_), 128, ATT_SMEM>>>();
    // 4) out = g_ao @ W_out^T  (mma.sync tf32)
    gemm_mma<<<dim3(D_ / 128, BL / 128), 256>>>(p_ao, Wout, out, D_, D_);
}

// round 9
// speedup vs baseline: 2.4948x; 1.5341x over previous
#include <cuda_runtime.h>
#include <math.h>
#include <float.h>
#include <cstdint>

#define B_  2
#define L_  2048
#define D_  1024
#define H_  16
#define DH  64
#define BL  (B_*L_)     // 4096
#define E3  (3*D_)      // 3072

// ---- scratch (static device globals; no allocation allowed) ----
__device__ float g_qkv[(size_t)BL * E3];      // 50 MB  raw qkv
__device__ float g_q[(size_t)B_*H_*L_*DH];    // 16 MB  [b,h,l,d]
__device__ float g_k[(size_t)B_*H_*L_*DH];
__device__ float g_v[(size_t)B_*H_*L_*DH];
__device__ float g_ao[(size_t)BL * D_];       // 16 MB  attention output [b,l,h*dh]

__device__ __forceinline__ uint32_t f2tf32(float x) {
    uint32_t r;
    asm("cvt.rna.tf32.f32 %0, %1;" : "=r"(r) : "f"(x));
    return r;
}
__device__ __forceinline__ float tfv(float x) { return __uint_as_float(f2tf32(x)); }

__device__ __forceinline__ void mma_tf32(float* d, const uint32_t* a, const uint32_t* b) {
    asm volatile(
        "mma.sync.aligned.m16n8k8.row.col.f32.tf32.tf32.f32 "
        "{%0,%1,%2,%3}, {%4,%5,%6,%7}, {%8,%9}, {%0,%1,%2,%3};"
        : "+f"(d[0]), "+f"(d[1]), "+f"(d[2]), "+f"(d[3])
        : "r"(a[0]), "r"(a[1]), "r"(a[2]), "r"(a[3]), "r"(b[0]), "r"(b[1]));
}

// ============================================================
// mma.sync tf32 GEMM: C[M,N] = A[M,K] * Bm[N,K]^T  (row-major A, Bm)
// ============================================================
#define KT 16
#define SST 20

__global__ __launch_bounds__(256, 2) void gemm_mma(const float* __restrict__ A,
                                                   const float* __restrict__ Bm,
                                                   float* __restrict__ C,
                                                   int N, int K) {
    __shared__ uint32_t As[2][128][SST];
    __shared__ uint32_t Bs[2][128][SST];

    int tid = threadIdx.x;
    int wid = tid >> 5, lane = tid & 31;
    int g = lane >> 2, tg = lane & 3;
    int wm = (wid & 1) * 64;
    int wn = (wid >> 1) * 32;
    int bn = blockIdx.x * 128;
    int bm = blockIdx.y * 128;
    const int NT = K / KT;

    int lr = tid >> 1;
    int lc = (tid & 1) * 8;

    const float* Ap = A  + (size_t)(bm + lr) * K + lc;
    const float* Bp = Bm + (size_t)(bn + lr) * K + lc;

    float4 ra0, ra1, rb0, rb1;
#define LOADG(k0) do { \
        ra0 = *(const float4*)(Ap + (k0));     ra1 = *(const float4*)(Ap + (k0) + 4); \
        rb0 = *(const float4*)(Bp + (k0));     rb1 = *(const float4*)(Bp + (k0) + 4); \
    } while (0)
#define STS(s) do { \
        As[s][lr][lc + 0] = f2tf32(ra0.x); As[s][lr][lc + 1] = f2tf32(ra0.y); \
        As[s][lr][lc + 2] = f2tf32(ra0.z); As[s][lr][lc + 3] = f2tf32(ra0.w); \
        As[s][lr][lc + 4] = f2tf32(ra1.x); As[s][lr][lc + 5] = f2tf32(ra1.y); \
        As[s][lr][lc + 6] = f2tf32(ra1.z); As[s][lr][lc + 7] = f2tf32(ra1.w); \
        Bs[s][lr][lc + 0] = f2tf32(rb0.x); Bs[s][lr][lc + 1] = f2tf32(rb0.y); \
        Bs[s][lr][lc + 2] = f2tf32(rb0.z); Bs[s][lr][lc + 3] = f2tf32(rb0.w); \
        Bs[s][lr][lc + 4] = f2tf32(rb1.x); Bs[s][lr][lc + 5] = f2tf32(rb1.y); \
        Bs[s][lr][lc + 6] = f2tf32(rb1.z); Bs[s][lr][lc + 7] = f2tf32(rb1.w); \
    } while (0)

    float acc[4][4][4];
#pragma unroll
    for (int mt = 0; mt < 4; mt++)
#pragma unroll
        for (int nt = 0; nt < 4; nt++)
#pragma unroll
            for (int q = 0; q < 4; q++) acc[mt][nt][q] = 0.0f;

    LOADG(0);
    STS(0);
    __syncthreads();

    for (int kt = 0; kt < NT; kt++) {
        if (kt + 1 < NT) LOADG((kt + 1) * KT);
        int s = kt & 1;
#pragma unroll
        for (int kk = 0; kk < KT; kk += 8) {
            uint32_t af[4][4], bf[4][2];
#pragma unroll
            for (int mt = 0; mt < 4; mt++) {
                int r0 = wm + mt * 16 + g;
                af[mt][0] = As[s][r0][kk + tg];
                af[mt][1] = As[s][r0 + 8][kk + tg];
                af[mt][2] = As[s][r0][kk + tg + 4];
                af[mt][3] = As[s][r0 + 8][kk + tg + 4];
            }
#pragma unroll
            for (int nt = 0; nt < 4; nt++) {
                int c0 = wn + nt * 8 + g;
                bf[nt][0] = Bs[s][c0][kk + tg];
                bf[nt][1] = Bs[s][c0][kk + tg + 4];
            }
#pragma unroll
            for (int mt = 0; mt < 4; mt++)
#pragma unroll
                for (int nt = 0; nt < 4; nt++)
                    mma_tf32(acc[mt][nt], af[mt], bf[nt]);
            // overlap STS of next stage with second kk-chunk's MMAs
            if (kk == 0 && kt + 1 < NT) STS((kt + 1) & 1);
        }
        __syncthreads();
    }

#pragma unroll
    for (int mt = 0; mt < 4; mt++) {
        int row = bm + wm + mt * 16 + g;
#pragma unroll
        for (int nt = 0; nt < 4; nt++) {
            int col = bn + wn + nt * 8 + 2 * tg;
            *(float2*)(C + (size_t)row * N + col)       = make_float2(acc[mt][nt][0], acc[mt][nt][1]);
            *(float2*)(C + (size_t)(row + 8) * N + col) = make_float2(acc[mt][nt][2], acc[mt][nt][3]);
        }
    }
#undef LOADG
#undef STS
}

// ============================================================
// RoPE + split/transpose
// ============================================================
__global__ __launch_bounds__(256) void rope_split(const int* __restrict__ pos_ids) {
    int idx = blockIdx.x * blockDim.x + threadIdx.x;
    int i = idx & 31;
    int rest = idx >> 5;
    int h = rest & 15;
    int rest2 = rest >> 4;
    int s = rest2 % 3;
    int bl = rest2 / 3;

    const float2 e = *(const float2*)(g_qkv + (size_t)bl * E3 + (s * H_ + h) * DH + 2 * i);

    int b = bl >> 11;
    int l = bl & (L_ - 1);
    size_t dst = ((size_t)(b * H_ + h) * L_ + l) * DH + 2 * i;

    if (s == 2) {
        *(float2*)(g_v + dst) = e;
    } else {
        float pos = (float)pos_ids[bl];
        float invf = powf(10000.0f, -(float)i * (1.0f / 32.0f));
        float ang = pos * invf;
        float cs, sn;
        sincosf(ang, &sn, &cs);
        float2 r;
        r.x = e.x * cs - e.y * sn;
        r.y = e.x * sn + e.y * cs;
        *(float2*)((s == 0 ? g_q : g_k) + dst) = r;
    }
}

// ============================================================
// Tensor-core causal flash attention (tf32 mma, 3xTF32 for QK^T).
// grid (L/64, B*H), 128 threads = 4 warps x 16 query rows.
// Changes vs prev round:
//  - K smem pair-interleaved {hi(k),lo(k),hi(k+4),lo(k+4)} -> 1 LDS.128 per B-frag
//  - K/V global loads register-prefetched one tile ahead (latency hidden)
// ============================================================
#define QKS 136          // Q hi/lo interleaved row stride (words)
#define KST 144          // K pair-interleaved row stride (words) — conflict-free
#define VST 72
#define PST 68
#define OQ  0
#define OK_ (64*QKS)                 // 8704
#define OV  (OK_ + 64*KST)           // +9216
#define OP  (OV + 64*VST)            // +4608
#define ATT_SMEM ((OP + 64*PST) * 4) // 107520 B

__global__ __launch_bounds__(128, 2) void attn_tc() {
    extern __shared__ float sm[];
    float* qhl = sm + OQ;
    float* khl = sm + OK_;
    float* vv  = sm + OV;
    float* pp  = sm + OP;

    int qt = gridDim.x - 1 - blockIdx.x;   // heavy tiles first
    int bh = blockIdx.y;
    int tid = threadIdx.x;
    int wid = tid >> 5, lane = tid & 31;
    int g = lane >> 2, tg = lane & 3;
    int rowb = wid * 16;

    const float* Qb = g_q + ((size_t)bh * L_ + qt * 64) * DH;

    // Q: scale by 1/8, hi/lo split, interleaved pairs (hi,lo) per element
#pragma unroll
    for (int it = 0; it < 8; it++) {
        int lin = it * 128 + tid;
        int r = lin >> 4, c = (lin & 15) * 4;
        float4 v = *(const float4*)(Qb + r * DH + c);
        float vals[4] = {v.x * 0.125f, v.y * 0.125f, v.z * 0.125f, v.w * 0.125f};
#pragma unroll
        for (int j = 0; j < 4; j++) {
            float hi = tfv(vals[j]);
            float lo = tfv(vals[j] - hi);
            *(float2*)(qhl + r * QKS + (c + j) * 2) = make_float2(hi, lo);
        }
    }

    // ---- K/V register prefetch buffers ----
    float4 pk[8], pv[8];
#define PREF(jtn) do { \
    const float* Kb_ = g_k + ((size_t)bh * L_ + (jtn) * 64) * DH; \
    const float* Vb_ = g_v + ((size_t)bh * L_ + (jtn) * 64) * DH; \
    _Pragma("unroll") \
    for (int it = 0; it < 8; it++) { \
        int lin = it * 128 + tid; \
        int r = lin >> 4; \
        int q16 = lin & 15; \
        int cc = q16 >> 1, jp = (q16 & 1) * 2; \
        int k0 = cc * 8 + jp; \
        float2 a_ = *(const float2*)(Kb_ + r * DH + k0); \
        float2 b_ = *(const float2*)(Kb_ + r * DH + k0 + 4); \
        pk[it] = make_float4(a_.x, a_.y, b_.x, b_.y); \
        int cv = (lin & 15) * 4; \
        pv[it] = *(const float4*)(Vb_ + r * DH + cv); \
    } } while (0)

    float o[8][4];
#pragma unroll
    for (int nt = 0; nt < 8; nt++)
#pragma unroll
        for (int q = 0; q < 4; q++) o[nt][q] = 0.0f;
    float mr0 = -1e30f, mr1 = -1e30f, lw0 = 0.0f, lw1 = 0.0f;

    PREF(0);

    for (int jt = 0; jt <= qt; jt++) {
        __syncthreads();   // previous tile fully consumed / Q ready
        // ---- store prefetched K (hi/lo pair-interleaved) and V (tf32) ----
#pragma unroll
        for (int it = 0; it < 8; it++) {
            int lin = it * 128 + tid;
            int r = lin >> 4;
            int q16 = lin & 15;
            int cc = q16 >> 1, jp = (q16 & 1) * 2;
            float4 kv = pk[it];
            // element pair (kv.x @ k0, kv.z @ k0+4) and (kv.y @ k0+1, kv.w @ k0+5)
            float hx = tfv(kv.x), hz = tfv(kv.z);
            float hy = tfv(kv.y), hw = tfv(kv.w);
            *(float4*)(khl + r * KST + cc * 16 + jp * 4) =
                make_float4(hx, tfv(kv.x - hx), hz, tfv(kv.z - hz));
            *(float4*)(khl + r * KST + cc * 16 + (jp + 1) * 4) =
                make_float4(hy, tfv(kv.y - hy), hw, tfv(kv.w - hw));
            int cv = (lin & 15) * 4;
            float4 vvv = pv[it];
            *(float4*)(vv + r * VST + cv) = make_float4(
                tfv(vvv.x), tfv(vvv.y), tfv(vvv.z), tfv(vvv.w));
        }
        if (jt < qt) PREF(jt + 1);    // hide next tile's LDG behind compute
        __syncthreads();

        // ---- S = Q K^T (3xTF32) ----
        float s[8][4];
#pragma unroll
        for (int nt = 0; nt < 8; nt++)
#pragma unroll
            for (int q = 0; q < 4; q++) s[nt][q] = 0.0f;

#pragma unroll
        for (int kk = 0; kk < 64; kk += 8) {
            int cc = kk >> 3;
            uint32_t ah[4], al[4];
            float2 t;
            t = *(const float2*)(qhl + (rowb + g) * QKS + (kk + tg) * 2);
            ah[0] = __float_as_uint(t.x); al[0] = __float_as_uint(t.y);
            t = *(const float2*)(qhl + (rowb + 8 + g) * QKS + (kk + tg) * 2);
            ah[1] = __float_as_uint(t.x); al[1] = __float_as_uint(t.y);
            t = *(const float2*)(qhl + (rowb + g) * QKS + (kk + tg + 4) * 2);
            ah[2] = __float_as_uint(t.x); al[2] = __float_as_uint(t.y);
            t = *(const float2*)(qhl + (rowb + 8 + g) * QKS + (kk + tg + 4) * 2);
            ah[3] = __float_as_uint(t.x); al[3] = __float_as_uint(t.y);
#pragma unroll
            for (int nt = 0; nt < 8; nt++) {
                float4 bq = *(const float4*)(khl + (nt * 8 + g) * KST + cc * 16 + tg * 4);
                uint32_t bhv[2] = {__float_as_uint(bq.x), __float_as_uint(bq.z)};
                uint32_t blv[2] = {__float_as_uint(bq.y), __float_as_uint(bq.w)};
                mma_tf32(s[nt], ah, bhv);
                mma_tf32(s[nt], al, bhv);
                mma_tf32(s[nt], ah, blv);
            }
        }

        // causal mask (diag tile only)
        if (jt == qt) {
            int r0 = rowb + g, r1 = rowb + 8 + g;
#pragma unroll
            for (int nt = 0; nt < 8; nt++) {
                int c0 = nt * 8 + 2 * tg;
                if (c0     > r0) s[nt][0] = -1e30f;
                if (c0 + 1 > r0) s[nt][1] = -1e30f;
                if (c0     > r1) s[nt][2] = -1e30f;
                if (c0 + 1 > r1) s[nt][3] = -1e30f;
            }
        }

        // ---- online softmax (rows g / g+8 within warp) ----
        float mx0 = -1e30f, mx1 = -1e30f;
#pragma unroll
        for (int nt = 0; nt < 8; nt++) {
            mx0 = fmaxf(mx0, fmaxf(s[nt][0], s[nt][1]));
            mx1 = fmaxf(mx1, fmaxf(s[nt][2], s[nt][3]));
        }
        mx0 = fmaxf(mx0, __shfl_xor_sync(0xffffffffu, mx0, 1));
        mx0 = fmaxf(mx0, __shfl_xor_sync(0xffffffffu, mx0, 2));
        mx1 = fmaxf(mx1, __shfl_xor_sync(0xffffffffu, mx1, 1));
        mx1 = fmaxf(mx1, __shfl_xor_sync(0xffffffffu, mx1, 2));
        float mn0 = fmaxf(mr0, mx0), mn1 = fmaxf(mr1, mx1);
        float cr0 = __expf(mr0 - mn0), cr1 = __expf(mr1 - mn1);
        float sum0 = 0.0f, sum1 = 0.0f;
#pragma unroll
        for (int nt = 0; nt < 8; nt++) {
            s[nt][0] = __expf(s[nt][0] - mn0);
            s[nt][1] = __expf(s[nt][1] - mn0);
            s[nt][2] = __expf(s[nt][2] - mn1);
            s[nt][3] = __expf(s[nt][3] - mn1);
            sum0 += s[nt][0] + s[nt][1];
            sum1 += s[nt][2] + s[nt][3];
        }
        sum0 += __shfl_xor_sync(0xffffffffu, sum0, 1);
        sum0 += __shfl_xor_sync(0xffffffffu, sum0, 2);
        sum1 += __shfl_xor_sync(0xffffffffu, sum1, 1);
        sum1 += __shfl_xor_sync(0xffffffffu, sum1, 2);
        lw0 = lw0 * cr0 + sum0;
        lw1 = lw1 * cr1 + sum1;
        mr0 = mn0; mr1 = mn1;
#pragma unroll
        for (int nt = 0; nt < 8; nt++) {
            o[nt][0] *= cr0; o[nt][1] *= cr0;
            o[nt][2] *= cr1; o[nt][3] *= cr1;
        }

        // write P (tf32) — per-warp-private rows of pp
#pragma unroll
        for (int nt = 0; nt < 8; nt++) {
            int c0 = nt * 8 + 2 * tg;
            *(float2*)(pp + (rowb + g) * PST + c0) =
                make_float2(tfv(s[nt][0]), tfv(s[nt][1]));
            *(float2*)(pp + (rowb + 8 + g) * PST + c0) =
                make_float2(tfv(s[nt][2]), tfv(s[nt][3]));
        }
        __syncwarp();

        // ---- O += P V ----
#pragma unroll
        for (int kk = 0; kk < 64; kk += 8) {
            uint32_t af[4];
            af[0] = __float_as_uint(pp[(rowb + g) * PST + kk + tg]);
            af[1] = __float_as_uint(pp[(rowb + 8 + g) * PST + kk + tg]);
            af[2] = __float_as_uint(pp[(rowb + g) * PST + kk + tg + 4]);
            af[3] = __float_as_uint(pp[(rowb + 8 + g) * PST + kk + tg + 4]);
#pragma unroll
            for (int nt = 0; nt < 8; nt++) {
                uint32_t bf[2] = {
                    __float_as_uint(vv[(kk + tg) * VST + nt * 8 + g]),
                    __float_as_uint(vv[(kk + tg + 4) * VST + nt * 8 + g])};
                mma_tf32(o[nt], af, bf);
            }
        }
    }

    // epilogue
    float i0 = 1.0f / lw0, i1 = 1.0f / lw1;
    int b = bh >> 4, h = bh & 15;
    int r0 = qt * 64 + rowb + g, r1 = r0 + 8;
#pragma unroll
    for (int nt = 0; nt < 8; nt++) {
        int col = h * DH + nt * 8 + 2 * tg;
        *(float2*)(g_ao + (size_t)(b * L_ + r0) * D_ + col) =
            make_float2(o[nt][0] * i0, o[nt][1] * i0);
        *(float2*)(g_ao + (size_t)(b * L_ + r1) * D_ + col) =
            make_float2(o[nt][2] * i1, o[nt][3] * i1);
    }
#undef PREF
}

// ============================================================
extern "C" void kernel_launch(void* const* d_in, const int* in_sizes, int n_in,
                              void* d_out, int out_size) {
    const float* x    = (const float*)d_in[0];
    const float* Wqkv = (const float*)d_in[1];
    const float* Wout = (const float*)d_in[2];
    const int*   pos  = (const int*)d_in[3];
    float* out = (float*)d_out;

    float *p_qkv, *p_ao;
    cudaGetSymbolAddress((void**)&p_qkv, g_qkv);
    cudaGetSymbolAddress((void**)&p_ao, g_ao);

    cudaFuncSetAttribute(attn_tc, cudaFuncAttributeMaxDynamicSharedMemorySize, ATT_SMEM);

    // 1) qkv = x @ W_qkv^T   (mma.sync tf32)
    gemm_mma<<<dim3(E3 / 128, BL / 128), 256>>>(x, Wqkv, p_qkv, E3, D_);
    // 2) rope + split into head-major q,k,v
    rope_split<<<(BL * E3 / 2) / 256, 256>>>(pos);
    // 3) tensor-core causal flash attention -> g_ao
    attn_tc<<<dim3(L_ / 64, B_ * H_), 128, ATT_SMEM>>>();
    // 4) out = g_ao @ W_out^T  (mma.sync tf32)
    gemm_mma<<<dim3(D_ / 128, BL / 128), 256>>>(p_ao, Wout, out, D_, D_);
}

// round 10
// speedup vs baseline: 2.5668x; 1.0289x over previous
#include <cuda_runtime.h>
#include <math.h>
#include <float.h>
#include <cstdint>

#define B_  2
#define L_  2048
#define D_  1024
#define H_  16
#define DH  64
#define BL  (B_*L_)     // 4096
#define E3  (3*D_)      // 3072

// ---- scratch (static device globals; no allocation allowed) ----
__device__ float g_qkv[(size_t)BL * E3];      // raw qkv (fp32)
__device__ float g_q[(size_t)B_*H_*L_*DH];    // [b,h,l,d] fp32
__device__ float g_k[(size_t)B_*H_*L_*DH];
__device__ float g_v[(size_t)B_*H_*L_*DH];    // tf32-rounded
__device__ float g_ao[(size_t)BL * D_];       // attention out, tf32-rounded
__device__ float g_xc[(size_t)BL * D_];       // x   tf32-rounded
__device__ float g_wq[(size_t)E3 * D_];       // Wqkv tf32-rounded
__device__ float g_wo[(size_t)D_ * D_];       // Wout tf32-rounded

__device__ __forceinline__ uint32_t f2tf32(float x) {
    uint32_t r;
    asm("cvt.rna.tf32.f32 %0, %1;" : "=r"(r) : "f"(x));
    return r;
}
__device__ __forceinline__ float tfv(float x) { return __uint_as_float(f2tf32(x)); }

__device__ __forceinline__ uint32_t smem_u32(const void* p) {
    uint32_t a;
    asm("{ .reg .u64 t; cvta.to.shared.u64 t, %1; cvt.u32.u64 %0, t; }" : "=r"(a) : "l"(p));
    return a;
}

__device__ __forceinline__ void mma_tf32(float* d, const uint32_t* a, const uint32_t* b) {
    asm volatile(
        "mma.sync.aligned.m16n8k8.row.col.f32.tf32.tf32.f32 "
        "{%0,%1,%2,%3}, {%4,%5,%6,%7}, {%8,%9}, {%0,%1,%2,%3};"
        : "+f"(d[0]), "+f"(d[1]), "+f"(d[2]), "+f"(d[3])
        : "r"(a[0]), "r"(a[1]), "r"(a[2]), "r"(a[3]), "r"(b[0]), "r"(b[1]));
}

// ============================================================
// tf32 pre-conversion (vectorized)
// ============================================================
__global__ __launch_bounds__(256) void conv_tf32(const float4* __restrict__ src,
                                                 float4* __restrict__ dst, int n4) {
    int i = blockIdx.x * blockDim.x + threadIdx.x;
    if (i < n4) {
        float4 v = src[i];
        dst[i] = make_float4(tfv(v.x), tfv(v.y), tfv(v.z), tfv(v.w));
    }
}

// ============================================================
// cp.async 4-stage pipelined tf32 GEMM:
// C[M,N] = A[M,K] * Bm[N,K]^T, inputs already tf32-rounded fp32.
// 128x128 CTA tile, KT=16, 256 threads (8 warps 2x4).
// smem row stride 20 words -> all fragment LDS conflict-free.
// ============================================================
#define GKT 16
#define GAST 20
#define GSTGW (128*GAST)            // 2560 words per stage per matrix
#define GEMM_SMEM (8*GSTGW*4)       // 81920 B

__global__ __launch_bounds__(256, 2) void gemm_ca(const float* __restrict__ A,
                                                  const float* __restrict__ Bm,
                                                  float* __restrict__ C,
                                                  int N, int K) {
    extern __shared__ float gsm[];
    float* SA = gsm;                // [4][GSTGW]
    float* SB = gsm + 4 * GSTGW;
    uint32_t sbase = smem_u32(gsm);

    int tid = threadIdx.x;
    int wid = tid >> 5, lane = tid & 31;
    int g = lane >> 2, tg = lane & 3;
    int wm = (wid & 1) * 64;
    int wn = (wid >> 1) * 32;
    int bn = blockIdx.x * 128;
    int bm = blockIdx.y * 128;
    const int NT = K / GKT;

    int row = tid >> 1;             // 0..127
    int cp2 = (tid & 1) * 2;        // chunk pair: k words cp2*4 .. cp2*4+7

    const float* Ag = A  + (size_t)(bm + row) * K + cp2 * 4;
    const float* Bg = Bm + (size_t)(bn + row) * K + cp2 * 4;
    uint32_t sa0 = sbase + (uint32_t)(row * GAST + cp2 * 4) * 4u;
    uint32_t sb0 = sa0 + (uint32_t)(4 * GSTGW) * 4u;

#define ISSUE(kt_) do { \
        uint32_t s_ = (uint32_t)((kt_) & 3) * (GSTGW * 4u); \
        const float* ga_ = Ag + (kt_) * GKT; \
        const float* gb_ = Bg + (kt_) * GKT; \
        asm volatile("cp.async.ca.shared.global [%0], [%1], 16;" :: "r"(sa0 + s_), "l"(ga_)); \
        asm volatile("cp.async.ca.shared.global [%0], [%1], 16;" :: "r"(sa0 + s_ + 16u), "l"(ga_ + 4)); \
        asm volatile("cp.async.ca.shared.global [%0], [%1], 16;" :: "r"(sb0 + s_), "l"(gb_)); \
        asm volatile("cp.async.ca.shared.global [%0], [%1], 16;" :: "r"(sb0 + s_ + 16u), "l"(gb_ + 4)); \
        asm volatile("cp.async.commit_group;"); \
    } while (0)

    float acc[4][4][4];
#pragma unroll
    for (int mt = 0; mt < 4; mt++)
#pragma unroll
        for (int nt = 0; nt < 4; nt++)
#pragma unroll
            for (int q = 0; q < 4; q++) acc[mt][nt][q] = 0.0f;

    ISSUE(0); ISSUE(1); ISSUE(2);

    for (int kt = 0; kt < NT; kt++) {
        asm volatile("cp.async.wait_group 2;" ::: "memory");
        __syncthreads();
        const float* As_ = SA + (kt & 3) * GSTGW;
        const float* Bs_ = SB + (kt & 3) * GSTGW;
#pragma unroll
        for (int kk = 0; kk < GKT; kk += 8) {
            uint32_t af[4][4], bf[4][2];
#pragma unroll
            for (int mt = 0; mt < 4; mt++) {
                int r0 = (wm + mt * 16 + g) * GAST;
                int r8 = r0 + 8 * GAST;
                af[mt][0] = __float_as_uint(As_[r0 + kk + tg]);
                af[mt][1] = __float_as_uint(As_[r8 + kk + tg]);
                af[mt][2] = __float_as_uint(As_[r0 + kk + tg + 4]);
                af[mt][3] = __float_as_uint(As_[r8 + kk + tg + 4]);
            }
#pragma unroll
            for (int nt = 0; nt < 4; nt++) {
                int c0 = (wn + nt * 8 + g) * GAST;
                bf[nt][0] = __float_as_uint(Bs_[c0 + kk + tg]);
                bf[nt][1] = __float_as_uint(Bs_[c0 + kk + tg + 4]);
            }
#pragma unroll
            for (int mt = 0; mt < 4; mt++)
#pragma unroll
                for (int nt = 0; nt < 4; nt++)
                    mma_tf32(acc[mt][nt], af[mt], bf[nt]);
        }
        if (kt + 3 < NT) ISSUE(kt + 3);
        else asm volatile("cp.async.commit_group;");   // keep group count uniform
    }

#pragma unroll
    for (int mt = 0; mt < 4; mt++) {
        int rowc = bm + wm + mt * 16 + g;
#pragma unroll
        for (int nt = 0; nt < 4; nt++) {
            int col = bn + wn + nt * 8 + 2 * tg;
            *(float2*)(C + (size_t)rowc * N + col)       = make_float2(acc[mt][nt][0], acc[mt][nt][1]);
            *(float2*)(C + (size_t)(rowc + 8) * N + col) = make_float2(acc[mt][nt][2], acc[mt][nt][3]);
        }
    }
#undef ISSUE
}

// ============================================================
// RoPE + split/transpose (V written tf32-rounded)
// ============================================================
__global__ __launch_bounds__(256) void rope_split(const int* __restrict__ pos_ids) {
    int idx = blockIdx.x * blockDim.x + threadIdx.x;
    int i = idx & 31;
    int rest = idx >> 5;
    int h = rest & 15;
    int rest2 = rest >> 4;
    int s = rest2 % 3;
    int bl = rest2 / 3;

    const float2 e = *(const float2*)(g_qkv + (size_t)bl * E3 + (s * H_ + h) * DH + 2 * i);

    int b = bl >> 11;
    int l = bl & (L_ - 1);
    size_t dst = ((size_t)(b * H_ + h) * L_ + l) * DH + 2 * i;

    if (s == 2) {
        *(float2*)(g_v + dst) = make_float2(tfv(e.x), tfv(e.y));
    } else {
        float pos = (float)pos_ids[bl];
        float invf = powf(10000.0f, -(float)i * (1.0f / 32.0f));
        float ang = pos * invf;
        float cs, sn;
        sincosf(ang, &sn, &cs);
        float2 r;
        r.x = e.x * cs - e.y * sn;
        r.y = e.x * sn + e.y * cs;
        *(float2*)((s == 0 ? g_q : g_k) + dst) = r;
    }
}

// ============================================================
// Tensor-core causal flash attention (tf32 mma, 3xTF32 for QK^T).
// ============================================================
#define QKS 136
#define KST 144
#define VST 72
#define PST 68
#define OQ  0
#define OK_ (64*QKS)
#define OV  (OK_ + 64*KST)
#define OP  (OV + 64*VST)
#define ATT_SMEM ((OP + 64*PST) * 4)

__global__ __launch_bounds__(128, 2) void attn_tc() {
    extern __shared__ float sm[];
    float* qhl = sm + OQ;
    float* khl = sm + OK_;
    float* vv  = sm + OV;
    float* pp  = sm + OP;

    int qt = gridDim.x - 1 - blockIdx.x;
    int bh = blockIdx.y;
    int tid = threadIdx.x;
    int wid = tid >> 5, lane = tid & 31;
    int g = lane >> 2, tg = lane & 3;
    int rowb = wid * 16;

    const float* Qb = g_q + ((size_t)bh * L_ + qt * 64) * DH;

#pragma unroll
    for (int it = 0; it < 8; it++) {
        int lin = it * 128 + tid;
        int r = lin >> 4, c = (lin & 15) * 4;
        float4 v = *(const float4*)(Qb + r * DH + c);
        float vals[4] = {v.x * 0.125f, v.y * 0.125f, v.z * 0.125f, v.w * 0.125f};
#pragma unroll
        for (int j = 0; j < 4; j++) {
            float hi = tfv(vals[j]);
            float lo = tfv(vals[j] - hi);
            *(float2*)(qhl + r * QKS + (c + j) * 2) = make_float2(hi, lo);
        }
    }

    float4 pk[8], pv[8];
#define PREF(jtn) do { \
    const float* Kb_ = g_k + ((size_t)bh * L_ + (jtn) * 64) * DH; \
    const float* Vb_ = g_v + ((size_t)bh * L_ + (jtn) * 64) * DH; \
    _Pragma("unroll") \
    for (int it = 0; it < 8; it++) { \
        int lin = it * 128 + tid; \
        int r = lin >> 4; \
        int q16 = lin & 15; \
        int cc = q16 >> 1, jp = (q16 & 1) * 2; \
        int k0 = cc * 8 + jp; \
        float2 a_ = *(const float2*)(Kb_ + r * DH + k0); \
        float2 b_ = *(const float2*)(Kb_ + r * DH + k0 + 4); \
        pk[it] = make_float4(a_.x, a_.y, b_.x, b_.y); \
        int cv = (lin & 15) * 4; \
        pv[it] = *(const float4*)(Vb_ + r * DH + cv); \
    } } while (0)

    float o[8][4];
#pragma unroll
    for (int nt = 0; nt < 8; nt++)
#pragma unroll
        for (int q = 0; q < 4; q++) o[nt][q] = 0.0f;
    float mr0 = -1e30f, mr1 = -1e30f, lw0 = 0.0f, lw1 = 0.0f;

    PREF(0);

    for (int jt = 0; jt <= qt; jt++) {
        __syncthreads();
#pragma unroll
        for (int it = 0; it < 8; it++) {
            int lin = it * 128 + tid;
            int r = lin >> 4;
            int q16 = lin & 15;
            int cc = q16 >> 1, jp = (q16 & 1) * 2;
            float4 kv = pk[it];
            float hx = tfv(kv.x), hz = tfv(kv.z);
            float hy = tfv(kv.y), hw = tfv(kv.w);
            *(float4*)(khl + r * KST + cc * 16 + jp * 4) =
                make_float4(hx, tfv(kv.x - hx), hz, tfv(kv.z - hz));
            *(float4*)(khl + r * KST + cc * 16 + (jp + 1) * 4) =
                make_float4(hy, tfv(kv.y - hy), hw, tfv(kv.w - hw));
            int cv = (lin & 15) * 4;
            *(float4*)(vv + r * VST + cv) = pv[it];   // already tf32 from rope
        }
        if (jt < qt) PREF(jt + 1);
        __syncthreads();

        float s[8][4];
#pragma unroll
        for (int nt = 0; nt < 8; nt++)
#pragma unroll
            for (int q = 0; q < 4; q++) s[nt][q] = 0.0f;

#pragma unroll
        for (int kk = 0; kk < 64; kk += 8) {
            int cc = kk >> 3;
            uint32_t ah[4], al[4];
            float2 t;
            t = *(const float2*)(qhl + (rowb + g) * QKS + (kk + tg) * 2);
            ah[0] = __float_as_uint(t.x); al[0] = __float_as_uint(t.y);
            t = *(const float2*)(qhl + (rowb + 8 + g) * QKS + (kk + tg) * 2);
            ah[1] = __float_as_uint(t.x); al[1] = __float_as_uint(t.y);
            t = *(const float2*)(qhl + (rowb + g) * QKS + (kk + tg + 4) * 2);
            ah[2] = __float_as_uint(t.x); al[2] = __float_as_uint(t.y);
            t = *(const float2*)(qhl + (rowb + 8 + g) * QKS + (kk + tg + 4) * 2);
            ah[3] = __float_as_uint(t.x); al[3] = __float_as_uint(t.y);
#pragma unroll
            for (int nt = 0; nt < 8; nt++) {
                float4 bq = *(const float4*)(khl + (nt * 8 + g) * KST + cc * 16 + tg * 4);
                uint32_t bhv[2] = {__float_as_uint(bq.x), __float_as_uint(bq.z)};
                uint32_t blv[2] = {__float_as_uint(bq.y), __float_as_uint(bq.w)};
                mma_tf32(s[nt], ah, bhv);
                mma_tf32(s[nt], al, bhv);
                mma_tf32(s[nt], ah, blv);
            }
        }

        if (jt == qt) {
            int r0 = rowb + g, r1 = rowb + 8 + g;
#pragma unroll
            for (int nt = 0; nt < 8; nt++) {
                int c0 = nt * 8 + 2 * tg;
                if (c0     > r0) s[nt][0] = -1e30f;
                if (c0 + 1 > r0) s[nt][1] = -1e30f;
                if (c0     > r1) s[nt][2] = -1e30f;
                if (c0 + 1 > r1) s[nt][3] = -1e30f;
            }
        }

        float mx0 = -1e30f, mx1 = -1e30f;
#pragma unroll
        for (int nt = 0; nt < 8; nt++) {
            mx0 = fmaxf(mx0, fmaxf(s[nt][0], s[nt][1]));
            mx1 = fmaxf(mx1, fmaxf(s[nt][2], s[nt][3]));
        }
        mx0 = fmaxf(mx0, __shfl_xor_sync(0xffffffffu, mx0, 1));
        mx0 = fmaxf(mx0, __shfl_xor_sync(0xffffffffu, mx0, 2));
        mx1 = fmaxf(mx1, __shfl_xor_sync(0xffffffffu, mx1, 1));
        mx1 = fmaxf(mx1, __shfl_xor_sync(0xffffffffu, mx1, 2));
        float mn0 = fmaxf(mr0, mx0), mn1 = fmaxf(mr1, mx1);
        float cr0 = __expf(mr0 - mn0), cr1 = __expf(mr1 - mn1);
        float sum0 = 0.0f, sum1 = 0.0f;
#pragma unroll
        for (int nt = 0; nt < 8; nt++) {
            s[nt][0] = __expf(s[nt][0] - mn0);
            s[nt][1] = __expf(s[nt][1] - mn0);
            s[nt][2] = __expf(s[nt][2] - mn1);
            s[nt][3] = __expf(s[nt][3] - mn1);
            sum0 += s[nt][0] + s[nt][1];
            sum1 += s[nt][2] + s[nt][3];
        }
        sum0 += __shfl_xor_sync(0xffffffffu, sum0, 1);
        sum0 += __shfl_xor_sync(0xffffffffu, sum0, 2);
        sum1 += __shfl_xor_sync(0xffffffffu, sum1, 1);
        sum1 += __shfl_xor_sync(0xffffffffu, sum1, 2);
        lw0 = lw0 * cr0 + sum0;
        lw1 = lw1 * cr1 + sum1;
        mr0 = mn0; mr1 = mn1;
#pragma unroll
        for (int nt = 0; nt < 8; nt++) {
            o[nt][0] *= cr0; o[nt][1] *= cr0;
            o[nt][2] *= cr1; o[nt][3] *= cr1;
        }

#pragma unroll
        for (int nt = 0; nt < 8; nt++) {
            int c0 = nt * 8 + 2 * tg;
            *(float2*)(pp + (rowb + g) * PST + c0) =
                make_float2(tfv(s[nt][0]), tfv(s[nt][1]));
            *(float2*)(pp + (rowb + 8 + g) * PST + c0) =
                make_float2(tfv(s[nt][2]), tfv(s[nt][3]));
        }
        __syncwarp();

#pragma unroll
        for (int kk = 0; kk < 64; kk += 8) {
            uint32_t af[4];
            af[0] = __float_as_uint(pp[(rowb + g) * PST + kk + tg]);
            af[1] = __float_as_uint(pp[(rowb + 8 + g) * PST + kk + tg]);
            af[2] = __float_as_uint(pp[(rowb + g) * PST + kk + tg + 4]);
            af[3] = __float_as_uint(pp[(rowb + 8 + g) * PST + kk + tg + 4]);
#pragma unroll
            for (int nt = 0; nt < 8; nt++) {
                uint32_t bf[2] = {
                    __float_as_uint(vv[(kk + tg) * VST + nt * 8 + g]),
                    __float_as_uint(vv[(kk + tg + 4) * VST + nt * 8 + g])};
                mma_tf32(o[nt], af, bf);
            }
        }
    }

    // epilogue (tf32-rounded -> feeds out-proj GEMM directly)
    float i0 = 1.0f / lw0, i1 = 1.0f / lw1;
    int b = bh >> 4, h = bh & 15;
    int r0 = qt * 64 + rowb + g, r1 = r0 + 8;
#pragma unroll
    for (int nt = 0; nt < 8; nt++) {
        int col = h * DH + nt * 8 + 2 * tg;
        *(float2*)(g_ao + (size_t)(b * L_ + r0) * D_ + col) =
            make_float2(tfv(o[nt][0] * i0), tfv(o[nt][1] * i0));
        *(float2*)(g_ao + (size_t)(b * L_ + r1) * D_ + col) =
            make_float2(tfv(o[nt][2] * i1), tfv(o[nt][3] * i1));
    }
#undef PREF
}

// ============================================================
extern "C" void kernel_launch(void* const* d_in, const int* in_sizes, int n_in,
                              void* d_out, int out_size) {
    const float* x    = (const float*)d_in[0];
    const float* Wqkv = (const float*)d_in[1];
    const float* Wout = (const float*)d_in[2];
    const int*   pos  = (const int*)d_in[3];
    float* out = (float*)d_out;

    float *p_qkv, *p_ao, *p_xc, *p_wq, *p_wo;
    cudaGetSymbolAddress((void**)&p_qkv, g_qkv);
    cudaGetSymbolAddress((void**)&p_ao, g_ao);
    cudaGetSymbolAddress((void**)&p_xc, g_xc);
    cudaGetSymbolAddress((void**)&p_wq, g_wq);
    cudaGetSymbolAddress((void**)&p_wo, g_wo);

    cudaFuncSetAttribute(attn_tc, cudaFuncAttributeMaxDynamicSharedMemorySize, ATT_SMEM);
    cudaFuncSetAttribute(gemm_ca, cudaFuncAttributeMaxDynamicSharedMemorySize, GEMM_SMEM);

    // 0) pre-convert operands to tf32
    conv_tf32<<<(BL * D_ / 4 + 255) / 256, 256>>>((const float4*)x, (float4*)p_xc, BL * D_ / 4);
    conv_tf32<<<(E3 * D_ / 4 + 255) / 256, 256>>>((const float4*)Wqkv, (float4*)p_wq, E3 * D_ / 4);
    conv_tf32<<<(D_ * D_ / 4 + 255) / 256, 256>>>((const float4*)Wout, (float4*)p_wo, D_ * D_ / 4);

    // 1) qkv = x @ W_qkv^T   (cp.async pipelined tf32)
    gemm_ca<<<dim3(E3 / 128, BL / 128), 256, GEMM_SMEM>>>(p_xc, p_wq, p_qkv, E3, D_);
    // 2) rope + split into head-major q,k,v (v tf32)
    rope_split<<<(BL * E3 / 2) / 256, 256>>>(pos);
    // 3) tensor-core causal flash attention -> g_ao (tf32)
    attn_tc<<<dim3(L_ / 64, B_ * H_), 128, ATT_SMEM>>>();
    // 4) out = g_ao @ W_out^T
    gemm_ca<<<dim3(D_ / 128, BL / 128), 256, GEMM_SMEM>>>(p_ao, p_wo, out, D_, D_);
}

// round 12
// speedup vs baseline: 2.8743x; 1.1198x over previous
#include <cuda_runtime.h>
#include <math.h>
#include <float.h>
#include <cstdint>

#define B_  2
#define L_  2048
#define D_  1024
#define H_  16
#define DH  64
#define BL  (B_*L_)     // 4096
#define E3  (3*D_)      // 3072

// ---- scratch (static device globals; no allocation allowed) ----
__device__ float g_qkv[(size_t)BL * E3];      // raw qkv (fp32)
__device__ float g_qhl[(size_t)B_*H_*L_*128]; // Q hi/lo interleaved, pre-scaled  (32 MB)
__device__ float g_khl[(size_t)B_*H_*L_*128]; // K hi/lo pair-interleaved         (32 MB)
__device__ float g_v[(size_t)B_*H_*L_*DH];    // V tf32-rounded
__device__ float g_ao[(size_t)BL * D_];       // attention out, tf32-rounded
__device__ float g_xc[(size_t)BL * D_];       // x    tf32-rounded
__device__ float g_wq[(size_t)E3 * D_];       // Wqkv tf32-rounded
__device__ float g_wo[(size_t)D_ * D_];       // Wout tf32-rounded

__device__ __forceinline__ uint32_t f2tf32(float x) {
    uint32_t r;
    asm("cvt.rna.tf32.f32 %0, %1;" : "=r"(r) : "f"(x));
    return r;
}
__device__ __forceinline__ float tfv(float x) { return __uint_as_float(f2tf32(x)); }

__device__ __forceinline__ uint32_t smem_u32(const void* p) {
    uint32_t a;
    asm("{ .reg .u64 t; cvta.to.shared.u64 t, %1; cvt.u32.u64 %0, t; }" : "=r"(a) : "l"(p));
    return a;
}

__device__ __forceinline__ void mma_tf32(float* d, const uint32_t* a, const uint32_t* b) {
    asm volatile(
        "mma.sync.aligned.m16n8k8.row.col.f32.tf32.tf32.f32 "
        "{%0,%1,%2,%3}, {%4,%5,%6,%7}, {%8,%9}, {%0,%1,%2,%3};"
        : "+f"(d[0]), "+f"(d[1]), "+f"(d[2]), "+f"(d[3])
        : "r"(a[0]), "r"(a[1]), "r"(a[2]), "r"(a[3]), "r"(b[0]), "r"(b[1]));
}

#define LDSM4(rr, addr) \
    asm volatile("ldmatrix.sync.aligned.m8n8.x4.shared.b16 {%0,%1,%2,%3}, [%4];" \
        : "=r"((rr)[0]), "=r"((rr)[1]), "=r"((rr)[2]), "=r"((rr)[3]) : "r"(addr))

// ============================================================
// tf32 pre-conversion (vectorized)
// ============================================================
__global__ __launch_bounds__(256) void conv_tf32(const float4* __restrict__ src,
                                                 float4* __restrict__ dst, int n4) {
    int i = blockIdx.x * blockDim.x + threadIdx.x;
    if (i < n4) {
        float4 v = src[i];
        dst[i] = make_float4(tfv(v.x), tfv(v.y), tfv(v.z), tfv(v.w));
    }
}

// ============================================================
// cp.async pipelined tf32 GEMM with ldmatrix fragment loads.
// C[M,N] = A[M,K] * Bm[N,K]^T, inputs already tf32-rounded fp32.
// 128x128 CTA tile, KT=16, 4 stages, 256 threads (8 warps 2x4).
// ============================================================
#define GKT 16
#define GAST 20
#define GSTGW (128*GAST)
#define GEMM_SMEM (8*GSTGW*4)       // 81920 B

__global__ __launch_bounds__(256, 2) void gemm_ca(const float* __restrict__ A,
                                                  const float* __restrict__ Bm,
                                                  float* __restrict__ C,
                                                  int N, int K) {
    extern __shared__ float gsm[];
    uint32_t sbase = smem_u32(gsm);

    int tid = threadIdx.x;
    int wid = tid >> 5, lane = tid & 31;
    int g = lane >> 2, tg = lane & 3;
    int wm = (wid & 1) * 64;
    int wn = (wid >> 1) * 32;
    int bn = blockIdx.x * 128;
    int bm = blockIdx.y * 128;
    const int NT = K / GKT;

    int row = tid >> 1;
    int cp2 = (tid & 1) * 2;

    const float* Ag = A  + (size_t)(bm + row) * K + cp2 * 4;
    const float* Bg = Bm + (size_t)(bn + row) * K + cp2 * 4;
    uint32_t sa0 = sbase + (uint32_t)(row * GAST + cp2 * 4) * 4u;
    uint32_t sb0 = sa0 + (uint32_t)(4 * GSTGW) * 4u;

    // ldmatrix per-lane base addresses
    int lm = lane >> 3, lr = lane & 7;
    uint32_t a_lm = sbase + (uint32_t)(((wm + lr + (lm & 1) * 8) * GAST + (lm >> 1) * 4) * 4);
    uint32_t b_lm = sbase + (uint32_t)(4 * GSTGW) * 4u
                  + (uint32_t)(((wn + lr + (lm >> 1) * 8) * GAST + (lm & 1) * 4) * 4);

#define ISSUE(kt_) do { \
        uint32_t s_ = (uint32_t)((kt_) & 3) * (GSTGW * 4u); \
        const float* ga_ = Ag + (kt_) * GKT; \
        const float* gb_ = Bg + (kt_) * GKT; \
        asm volatile("cp.async.ca.shared.global [%0], [%1], 16;" :: "r"(sa0 + s_), "l"(ga_)); \
        asm volatile("cp.async.ca.shared.global [%0], [%1], 16;" :: "r"(sa0 + s_ + 16u), "l"(ga_ + 4)); \
        asm volatile("cp.async.ca.shared.global [%0], [%1], 16;" :: "r"(sb0 + s_), "l"(gb_)); \
        asm volatile("cp.async.ca.shared.global [%0], [%1], 16;" :: "r"(sb0 + s_ + 16u), "l"(gb_ + 4)); \
        asm volatile("cp.async.commit_group;"); \
    } while (0)

    float acc[4][4][4];
#pragma unroll
    for (int mt = 0; mt < 4; mt++)
#pragma unroll
        for (int nt = 0; nt < 4; nt++)
#pragma unroll
            for (int q = 0; q < 4; q++) acc[mt][nt][q] = 0.0f;

    ISSUE(0); ISSUE(1); ISSUE(2);

    for (int kt = 0; kt < NT; kt++) {
        asm volatile("cp.async.wait_group 2;" ::: "memory");
        __syncthreads();
        uint32_t stoff = (uint32_t)(kt & 3) * (GSTGW * 4u);
#pragma unroll
        for (int kk = 0; kk < GKT; kk += 8) {
            uint32_t af[4][4], bfm[2][4];
#pragma unroll
            for (int mt = 0; mt < 4; mt++)
                LDSM4(af[mt], a_lm + stoff + (uint32_t)((mt * 16 * GAST + kk) * 4));
#pragma unroll
            for (int p = 0; p < 2; p++)
                LDSM4(bfm[p], b_lm + stoff + (uint32_t)((p * 16 * GAST + kk) * 4));
#pragma unroll
            for (int mt = 0; mt < 4; mt++)
#pragma unroll
                for (int nt = 0; nt < 4; nt++)
                    mma_tf32(acc[mt][nt], af[mt], &bfm[nt >> 1][(nt & 1) * 2]);
        }
        if (kt + 3 < NT) ISSUE(kt + 3);
        else asm volatile("cp.async.commit_group;");
    }

#pragma unroll
    for (int mt = 0; mt < 4; mt++) {
        int rowc = bm + wm + mt * 16 + g;
#pragma unroll
        for (int nt = 0; nt < 4; nt++) {
            int col = bn + wn + nt * 8 + 2 * tg;
            *(float2*)(C + (size_t)rowc * N + col)       = make_float2(acc[mt][nt][0], acc[mt][nt][1]);
            *(float2*)(C + (size_t)(rowc + 8) * N + col) = make_float2(acc[mt][nt][2], acc[mt][nt][3]);
        }
    }
#undef ISSUE
}

// ============================================================
// RoPE + split/transpose. Writes:
//  Q: hi/lo interleaved (word 2k = hi, 2k+1 = lo), pre-scaled by 1/8
//  K: hi/lo pair-interleaved {hi(k0),lo(k0),hi(k0+4),lo(k0+4)} per 16B
//  V: tf32-rounded plain [bh][l][64]
// ============================================================
__global__ __launch_bounds__(256) void rope_split(const int* __restrict__ pos_ids) {
    int idx = blockIdx.x * blockDim.x + threadIdx.x;
    int i = idx & 31;
    int rest = idx >> 5;
    int h = rest & 15;
    int rest2 = rest >> 4;
    int s = rest2 % 3;
    int bl = rest2 / 3;

    const float2 e = *(const float2*)(g_qkv + (size_t)bl * E3 + (s * H_ + h) * DH + 2 * i);

    int b = bl >> 11;
    int l = bl & (L_ - 1);
    size_t bh_row = (size_t)(b * H_ + h) * L_ + l;

    if (s == 2) {
        *(float2*)(g_v + bh_row * DH + 2 * i) = make_float2(tfv(e.x), tfv(e.y));
    } else {
        float pos = (float)pos_ids[bl];
        float invf = powf(10000.0f, -(float)i * (1.0f / 32.0f));
        float ang = pos * invf;
        float cs, sn;
        sincosf(ang, &sn, &cs);
        float rx = e.x * cs - e.y * sn;
        float ry = e.x * sn + e.y * cs;
        int k0 = 2 * i, k1 = 2 * i + 1;
        if (s == 0) {
            rx *= 0.125f; ry *= 0.125f;
            float hx = tfv(rx), hy = tfv(ry);
            float* dst = g_qhl + bh_row * 128;
            *(float2*)(dst + 2 * k0) = make_float2(hx, tfv(rx - hx));
            *(float2*)(dst + 2 * k1) = make_float2(hy, tfv(ry - hy));
        } else {
            float hx = tfv(rx), hy = tfv(ry);
            int w0 = ((k0 >> 3) << 4) + ((k0 & 3) << 2) + (((k0 >> 2) & 1) << 1);
            int w1 = ((k1 >> 3) << 4) + ((k1 & 3) << 2) + (((k1 >> 2) & 1) << 1);
            float* dst = g_khl + bh_row * 128;
            *(float2*)(dst + w0) = make_float2(hx, tfv(rx - hx));
            *(float2*)(dst + w1) = make_float2(hy, tfv(ry - hy));
        }
    }
}

// ============================================================
// Tensor-core causal flash attention (tf32 mma, 3xTF32 for QK^T).
// Staging is now pure copy (hi/lo precomputed globally).
// ============================================================
#define QKS 136
#define KST 144
#define VST 72
#define PST 68
#define OQ  0
#define OK_ (64*QKS)
#define OV  (OK_ + 64*KST)
#define OP  (OV + 64*VST)
#define ATT_SMEM ((OP + 64*PST) * 4)

__global__ __launch_bounds__(128, 2) void attn_tc() {
    extern __shared__ float sm[];
    float* qhl = sm + OQ;
    float* khl = sm + OK_;
    float* vv  = sm + OV;
    float* pp  = sm + OP;

    int qt = gridDim.x - 1 - blockIdx.x;
    int bh = blockIdx.y;
    int tid = threadIdx.x;
    int wid = tid >> 5, lane = tid & 31;
    int g = lane >> 2, tg = lane & 3;
    int rowb = wid * 16;

    // Q copy (already scaled + hi/lo interleaved)
    {
        const float* Qb = g_qhl + ((size_t)bh * L_ + qt * 64) * 128;
#pragma unroll
        for (int it = 0; it < 16; it++) {
            int lin = it * 128 + tid;
            float4 v = *(const float4*)(Qb + lin * 4);
            int r = lin >> 5, u = lin & 31;
            *(float4*)(qhl + r * QKS + u * 4) = v;
        }
    }

    float4 pk[16], pv[8];
#define PREF(jtn) do { \
    const float* Kb_ = g_khl + ((size_t)bh * L_ + (jtn) * 64) * 128; \
    const float* Vb_ = g_v + ((size_t)bh * L_ + (jtn) * 64) * DH; \
    _Pragma("unroll") \
    for (int it = 0; it < 16; it++) \
        pk[it] = *(const float4*)(Kb_ + (it * 128 + tid) * 4); \
    _Pragma("unroll") \
    for (int it = 0; it < 8; it++) \
        pv[it] = *(const float4*)(Vb_ + (it * 128 + tid) * 4); \
    } while (0)

    float o[8][4];
#pragma unroll
    for (int nt = 0; nt < 8; nt++)
#pragma unroll
        for (int q = 0; q < 4; q++) o[nt][q] = 0.0f;
    float mr0 = -1e30f, mr1 = -1e30f, lw0 = 0.0f, lw1 = 0.0f;

    PREF(0);

    for (int jt = 0; jt <= qt; jt++) {
        __syncthreads();
        // pure-copy staging
#pragma unroll
        for (int it = 0; it < 16; it++) {
            int lin = it * 128 + tid;
            int r = lin >> 5, u = lin & 31;
            *(float4*)(khl + r * KST + u * 4) = pk[it];
        }
#pragma unroll
        for (int it = 0; it < 8; it++) {
            int lin = it * 128 + tid;
            int r = lin >> 4, u = lin & 15;
            *(float4*)(vv + r * VST + u * 4) = pv[it];
        }
        if (jt < qt) PREF(jt + 1);
        __syncthreads();

        // ---- S = Q K^T (3xTF32) ----
        float s[8][4];
#pragma unroll
        for (int nt = 0; nt < 8; nt++)
#pragma unroll
            for (int q = 0; q < 4; q++) s[nt][q] = 0.0f;

#pragma unroll
        for (int kk = 0; kk < 64; kk += 8) {
            int cc = kk >> 3;
            uint32_t ah[4], al[4];
            float2 t;
            t = *(const float2*)(qhl + (rowb + g) * QKS + (kk + tg) * 2);
            ah[0] = __float_as_uint(t.x); al[0] = __float_as_uint(t.y);
            t = *(const float2*)(qhl + (rowb + 8 + g) * QKS + (kk + tg) * 2);
            ah[1] = __float_as_uint(t.x); al[1] = __float_as_uint(t.y);
            t = *(const float2*)(qhl + (rowb + g) * QKS + (kk + tg + 4) * 2);
            ah[2] = __float_as_uint(t.x); al[2] = __float_as_uint(t.y);
            t = *(const float2*)(qhl + (rowb + 8 + g) * QKS + (kk + tg + 4) * 2);
            ah[3] = __float_as_uint(t.x); al[3] = __float_as_uint(t.y);
#pragma unroll
            for (int nt = 0; nt < 8; nt++) {
                float4 bq = *(const float4*)(khl + (nt * 8 + g) * KST + cc * 16 + tg * 4);
                uint32_t bhv[2] = {__float_as_uint(bq.x), __float_as_uint(bq.z)};
                uint32_t blv[2] = {__float_as_uint(bq.y), __float_as_uint(bq.w)};
                mma_tf32(s[nt], ah, bhv);
                mma_tf32(s[nt], al, bhv);
                mma_tf32(s[nt], ah, blv);
            }
        }

        if (jt == qt) {
            int r0 = rowb + g, r1 = rowb + 8 + g;
#pragma unroll
            for (int nt = 0; nt < 8; nt++) {
                int c0 = nt * 8 + 2 * tg;
                if (c0     > r0) s[nt][0] = -1e30f;
                if (c0 + 1 > r0) s[nt][1] = -1e30f;
                if (c0     > r1) s[nt][2] = -1e30f;
                if (c0 + 1 > r1) s[nt][3] = -1e30f;
            }
        }

        float mx0 = -1e30f, mx1 = -1e30f;
#pragma unroll
        for (int nt = 0; nt < 8; nt++) {
            mx0 = fmaxf(mx0, fmaxf(s[nt][0], s[nt][1]));
            mx1 = fmaxf(mx1, fmaxf(s[nt][2], s[nt][3]));
        }
        mx0 = fmaxf(mx0, __shfl_xor_sync(0xffffffffu, mx0, 1));
        mx0 = fmaxf(mx0, __shfl_xor_sync(0xffffffffu, mx0, 2));
        mx1 = fmaxf(mx1, __shfl_xor_sync(0xffffffffu, mx1, 1));
        mx1 = fmaxf(mx1, __shfl_xor_sync(0xffffffffu, mx1, 2));
        float mn0 = fmaxf(mr0, mx0), mn1 = fmaxf(mr1, mx1);
        float cr0 = __expf(mr0 - mn0), cr1 = __expf(mr1 - mn1);
        float sum0 = 0.0f, sum1 = 0.0f;
#pragma unroll
        for (int nt = 0; nt < 8; nt++) {
            s[nt][0] = __expf(s[nt][0] - mn0);
            s[nt][1] = __expf(s[nt][1] - mn0);
            s[nt][2] = __expf(s[nt][2] - mn1);
            s[nt][3] = __expf(s[nt][3] - mn1);
            sum0 += s[nt][0] + s[nt][1];
            sum1 += s[nt][2] + s[nt][3];
        }
        sum0 += __shfl_xor_sync(0xffffffffu, sum0, 1);
        sum0 += __shfl_xor_sync(0xffffffffu, sum0, 2);
        sum1 += __shfl_xor_sync(0xffffffffu, sum1, 1);
        sum1 += __shfl_xor_sync(0xffffffffu, sum1, 2);
        lw0 = lw0 * cr0 + sum0;
        lw1 = lw1 * cr1 + sum1;
        mr0 = mn0; mr1 = mn1;
#pragma unroll
        for (int nt = 0; nt < 8; nt++) {
            o[nt][0] *= cr0; o[nt][1] *= cr0;
            o[nt][2] *= cr1; o[nt][3] *= cr1;
        }

#pragma unroll
        for (int nt = 0; nt < 8; nt++) {
            int c0 = nt * 8 + 2 * tg;
            *(float2*)(pp + (rowb + g) * PST + c0) =
                make_float2(tfv(s[nt][0]), tfv(s[nt][1]));
            *(float2*)(pp + (rowb + 8 + g) * PST + c0) =
                make_float2(tfv(s[nt][2]), tfv(s[nt][3]));
        }
        __syncwarp();

#pragma unroll
        for (int kk = 0; kk < 64; kk += 8) {
            uint32_t af[4];
            af[0] = __float_as_uint(pp[(rowb + g) * PST + kk + tg]);
            af[1] = __float_as_uint(pp[(rowb + 8 + g) * PST + kk + tg]);
            af[2] = __float_as_uint(pp[(rowb + g) * PST + kk + tg + 4]);
            af[3] = __float_as_uint(pp[(rowb + 8 + g) * PST + kk + tg + 4]);
#pragma unroll
            for (int nt = 0; nt < 8; nt++) {
                uint32_t bf[2] = {
                    __float_as_uint(vv[(kk + tg) * VST + nt * 8 + g]),
                    __float_as_uint(vv[(kk + tg + 4) * VST + nt * 8 + g])};
                mma_tf32(o[nt], af, bf);
            }
        }
    }

    // epilogue (tf32-rounded -> feeds out-proj GEMM directly)
    float i0 = 1.0f / lw0, i1 = 1.0f / lw1;
    int b = bh >> 4, h = bh & 15;
    int r0 = qt * 64 + rowb + g, r1 = r0 + 8;
#pragma unroll
    for (int nt = 0; nt < 8; nt++) {
        int col = h * DH + nt * 8 + 2 * tg;
        *(float2*)(g_ao + (size_t)(b * L_ + r0) * D_ + col) =
            make_float2(tfv(o[nt][0] * i0), tfv(o[nt][1] * i0));
        *(float2*)(g_ao + (size_t)(b * L_ + r1) * D_ + col) =
            make_float2(tfv(o[nt][2] * i1), tfv(o[nt][3] * i1));
    }
#undef PREF
}

// ============================================================
extern "C" void kernel_launch(void* const* d_in, const int* in_sizes, int n_in,
                              void* d_out, int out_size) {
    const float* x    = (const float*)d_in[0];
    const float* Wqkv = (const float*)d_in[1];
    const float* Wout = (const float*)d_in[2];
    const int*   pos  = (const int*)d_in[3];
    float* out = (float*)d_out;

    float *p_qkv, *p_ao, *p_xc, *p_wq, *p_wo;
    cudaGetSymbolAddress((void**)&p_qkv, g_qkv);
    cudaGetSymbolAddress((void**)&p_ao, g_ao);
    cudaGetSymbolAddress((void**)&p_xc, g_xc);
    cudaGetSymbolAddress((void**)&p_wq, g_wq);
    cudaGetSymbolAddress((void**)&p_wo, g_wo);

    cudaFuncSetAttribute(attn_tc, cudaFuncAttributeMaxDynamicSharedMemorySize, ATT_SMEM);
    cudaFuncSetAttribute(gemm_ca, cudaFuncAttributeMaxDynamicSharedMemorySize, GEMM_SMEM);

    // 0) pre-convert operands to tf32
    conv_tf32<<<(BL * D_ / 4 + 255) / 256, 256>>>((const float4*)x, (float4*)p_xc, BL * D_ / 4);
    conv_tf32<<<(E3 * D_ / 4 + 255) / 256, 256>>>((const float4*)Wqkv, (float4*)p_wq, E3 * D_ / 4);
    conv_tf32<<<(D_ * D_ / 4 + 255) / 256, 256>>>((const float4*)Wout, (float4*)p_wo, D_ * D_ / 4);

    // 1) qkv = x @ W_qkv^T   (cp.async + ldmatrix tf32)
    gemm_ca<<<dim3(E3 / 128, BL / 128), 256, GEMM_SMEM>>>(p_xc, p_wq, p_qkv, E3, D_);
    // 2) rope + split -> qhl/khl (hi/lo) + v (tf32)
    rope_split<<<(BL * E3 / 2) / 256, 256>>>(pos);
    // 3) tensor-core causal flash attention -> g_ao (tf32)
    attn_tc<<<dim3(L_ / 64, B_ * H_), 128, ATT_SMEM>>>();
    // 4) out = g_ao @ W_out^T
    gemm_ca<<<dim3(D_ / 128, BL / 128), 256, GEMM_SMEM>>>(p_ao, p_wo, out, D_, D_);
}

// round 14
// speedup vs baseline: 3.2131x; 1.1179x over previous
#include <cuda_runtime.h>
#include <math.h>
#include <float.h>
#include <cstdint>

#define B_  2
#define L_  2048
#define D_  1024
#define H_  16
#define DH  64
#define BL  (B_*L_)     // 4096
#define E3  (3*D_)      // 3072

// ---- scratch (static device globals; no allocation allowed) ----
__device__ float g_qkv[(size_t)BL * E3];      // raw qkv (fp32)
__device__ float g_qhl[(size_t)B_*H_*L_*128]; // Q hi/lo interleaved, pre-scaled
__device__ float g_khl[(size_t)B_*H_*L_*128]; // K hi/lo pair-interleaved
__device__ float g_v[(size_t)B_*H_*L_*DH];    // V tf32-rounded
__device__ float g_ao[(size_t)BL * D_];       // attention out, tf32-rounded
__device__ float g_xc[(size_t)BL * D_];       // x    tf32-rounded
__device__ float g_wq[(size_t)E3 * D_];       // Wqkv tf32-rounded
__device__ float g_wo[(size_t)D_ * D_];       // Wout tf32-rounded

__device__ __forceinline__ uint32_t f2tf32(float x) {
    uint32_t r;
    asm("cvt.rna.tf32.f32 %0, %1;" : "=r"(r) : "f"(x));
    return r;
}
__device__ __forceinline__ float tfv(float x) { return __uint_as_float(f2tf32(x)); }

__device__ __forceinline__ uint32_t smem_u32(const void* p) {
    uint32_t a;
    asm("{ .reg .u64 t; cvta.to.shared.u64 t, %1; cvt.u32.u64 %0, t; }" : "=r"(a) : "l"(p));
    return a;
}

__device__ __forceinline__ void mma_tf32(float* d, const uint32_t* a, const uint32_t* b) {
    asm volatile(
        "mma.sync.aligned.m16n8k8.row.col.f32.tf32.tf32.f32 "
        "{%0,%1,%2,%3}, {%4,%5,%6,%7}, {%8,%9}, {%0,%1,%2,%3};"
        : "+f"(d[0]), "+f"(d[1]), "+f"(d[2]), "+f"(d[3])
        : "r"(a[0]), "r"(a[1]), "r"(a[2]), "r"(a[3]), "r"(b[0]), "r"(b[1]));
}

#define LDSM4(rr, addr) \
    asm volatile("ldmatrix.sync.aligned.m8n8.x4.shared.b16 {%0,%1,%2,%3}, [%4];" \
        : "=r"((rr)[0]), "=r"((rr)[1]), "=r"((rr)[2]), "=r"((rr)[3]) : "r"(addr))

#define CPA16(dst, src) \
    asm volatile("cp.async.ca.shared.global [%0], [%1], 16;" :: "r"(dst), "l"(src))
#define CPCOMMIT() asm volatile("cp.async.commit_group;")

// ============================================================
// tf32 pre-conversion
// ============================================================
__global__ __launch_bounds__(256) void conv_tf32(const float4* __restrict__ src,
                                                 float4* __restrict__ dst, int n4) {
    int i = blockIdx.x * blockDim.x + threadIdx.x;
    if (i < n4) {
        float4 v = src[i];
        dst[i] = make_float4(tfv(v.x), tfv(v.y), tfv(v.z), tfv(v.w));
    }
}

// ============================================================
// cp.async pipelined tf32 GEMM, CTA tile 128x256, warp tile 64x64.
// C[M,N] = A[M,K] * Bm[N,K]^T, inputs already tf32-rounded.
// 256 threads (8 warps 2x4), KT=16, 4 stages, ldmatrix fragments.
// ============================================================
#define GKT 16
#define GAST 20
#define ASTG (128*GAST)             // 2560 words per A stage
#define BSTG (256*GAST)             // 5120 words per B stage
#define SBOFF (4*ASTG)              // B region word offset
#define GEMM_SMEM ((4*ASTG + 4*BSTG)*4)   // 122880 B

__global__ __launch_bounds__(256, 1) void gemm_ca(const float* __restrict__ A,
                                                  const float* __restrict__ Bm,
                                                  float* __restrict__ C,
                                                  int N, int K) {
    extern __shared__ float gsm[];
    uint32_t sbase = smem_u32(gsm);

    int tid = threadIdx.x;
    int wid = tid >> 5, lane = tid & 31;
    int g = lane >> 2, tg = lane & 3;
    int wm = (wid & 1) * 64;
    int wn = (wid >> 1) * 64;
    int bn = blockIdx.x * 256;
    int bm = blockIdx.y * 128;
    const int NT = K / GKT;

    // A loads: 2 threads/row, 2 chunks each. B loads: 1 thread/row, 4 chunks.
    int rowA = tid >> 1;
    int cp2 = (tid & 1) * 2;
    const float* Ag = A  + (size_t)(bm + rowA) * K + cp2 * 4;
    const float* Bg = Bm + (size_t)(bn + tid) * K;
    uint32_t sa0 = sbase + (uint32_t)(rowA * GAST + cp2 * 4) * 4u;
    uint32_t sb0 = sbase + (uint32_t)(SBOFF + tid * GAST) * 4u;

    // ldmatrix lane addressing
    // A tiles: bit0 of (lane>>3) = m-row block, bit1 = k block
    int lm = lane >> 3, lr8 = lane & 7;
    uint32_t a_lm = sbase + (uint32_t)(((wm + lr8 + (lm & 1) * 8) * GAST + (lm >> 1) * 4) * 4);
    // B tiles: bit0 = k block, bit1 = n-row block  (required by bfm[nt>>1][(nt&1)*2])
    uint32_t b_lm = sbase + (uint32_t)((SBOFF + (wn + lr8 + (lm >> 1) * 8) * GAST + (lm & 1) * 4) * 4);

#define ISSUE(kt_) do { \
        uint32_t sa_ = (uint32_t)((kt_) & 3) * (ASTG * 4u); \
        uint32_t sb_ = (uint32_t)((kt_) & 3) * (BSTG * 4u); \
        const float* ga_ = Ag + (kt_) * GKT; \
        const float* gb_ = Bg + (kt_) * GKT; \
        CPA16(sa0 + sa_,        ga_); \
        CPA16(sa0 + sa_ + 16u,  ga_ + 4); \
        CPA16(sb0 + sb_,        gb_); \
        CPA16(sb0 + sb_ + 16u,  gb_ + 4); \
        CPA16(sb0 + sb_ + 32u,  gb_ + 8); \
        CPA16(sb0 + sb_ + 48u,  gb_ + 12); \
        CPCOMMIT(); \
    } while (0)

    float acc[4][8][4];
#pragma unroll
    for (int mt = 0; mt < 4; mt++)
#pragma unroll
        for (int nt = 0; nt < 8; nt++)
#pragma unroll
            for (int q = 0; q < 4; q++) acc[mt][nt][q] = 0.0f;

    ISSUE(0); ISSUE(1); ISSUE(2);

    for (int kt = 0; kt < NT; kt++) {
        asm volatile("cp.async.wait_group 2;" ::: "memory");
        __syncthreads();
        uint32_t saoff = (uint32_t)(kt & 3) * (ASTG * 4u);
        uint32_t sboff = (uint32_t)(kt & 3) * (BSTG * 4u);
#pragma unroll
        for (int kk = 0; kk < GKT; kk += 8) {
            uint32_t af[4][4], bfm[4][4];
#pragma unroll
            for (int mt = 0; mt < 4; mt++)
                LDSM4(af[mt], a_lm + saoff + (uint32_t)((mt * 16 * GAST + kk) * 4));
#pragma unroll
            for (int p = 0; p < 4; p++)
                LDSM4(bfm[p], b_lm + sboff + (uint32_t)((p * 16 * GAST + kk) * 4));
#pragma unroll
            for (int mt = 0; mt < 4; mt++)
#pragma unroll
                for (int nt = 0; nt < 8; nt++)
                    mma_tf32(acc[mt][nt], af[mt], &bfm[nt >> 1][(nt & 1) * 2]);
        }
        if (kt + 3 < NT) ISSUE(kt + 3);
        else CPCOMMIT();
    }

#pragma unroll
    for (int mt = 0; mt < 4; mt++) {
        int rowc = bm + wm + mt * 16 + g;
#pragma unroll
        for (int nt = 0; nt < 8; nt++) {
            int col = bn + wn + nt * 8 + 2 * tg;
            *(float2*)(C + (size_t)rowc * N + col)       = make_float2(acc[mt][nt][0], acc[mt][nt][1]);
            *(float2*)(C + (size_t)(rowc + 8) * N + col) = make_float2(acc[mt][nt][2], acc[mt][nt][3]);
        }
    }
#undef ISSUE
}

// ============================================================
// RoPE + split (unchanged layouts)
// ============================================================
__global__ __launch_bounds__(256) void rope_split(const int* __restrict__ pos_ids) {
    int idx = blockIdx.x * blockDim.x + threadIdx.x;
    int i = idx & 31;
    int rest = idx >> 5;
    int h = rest & 15;
    int rest2 = rest >> 4;
    int s = rest2 % 3;
    int bl = rest2 / 3;

    const float2 e = *(const float2*)(g_qkv + (size_t)bl * E3 + (s * H_ + h) * DH + 2 * i);

    int b = bl >> 11;
    int l = bl & (L_ - 1);
    size_t bh_row = (size_t)(b * H_ + h) * L_ + l;

    if (s == 2) {
        *(float2*)(g_v + bh_row * DH + 2 * i) = make_float2(tfv(e.x), tfv(e.y));
    } else {
        float pos = (float)pos_ids[bl];
        float invf = powf(10000.0f, -(float)i * (1.0f / 32.0f));
        float ang = pos * invf;
        float cs, sn;
        sincosf(ang, &sn, &cs);
        float rx = e.x * cs - e.y * sn;
        float ry = e.x * sn + e.y * cs;
        int k0 = 2 * i, k1 = 2 * i + 1;
        if (s == 0) {
            rx *= 0.125f; ry *= 0.125f;
            float hx = tfv(rx), hy = tfv(ry);
            float* dst = g_qhl + bh_row * 128;
            *(float2*)(dst + 2 * k0) = make_float2(hx, tfv(rx - hx));
            *(float2*)(dst + 2 * k1) = make_float2(hy, tfv(ry - hy));
        } else {
            float hx = tfv(rx), hy = tfv(ry);
            int w0 = ((k0 >> 3) << 4) + ((k0 & 3) << 2) + (((k0 >> 2) & 1) << 1);
            int w1 = ((k1 >> 3) << 4) + ((k1 & 3) << 2) + (((k1 >> 2) & 1) << 1);
            float* dst = g_khl + bh_row * 128;
            *(float2*)(dst + w0) = make_float2(hx, tfv(rx - hx));
            *(float2*)(dst + w1) = make_float2(hy, tfv(ry - hy));
        }
    }
}

// ============================================================
// Tensor-core causal flash attention.
// Q fragments in registers (from g_qhl); K 2-stage + V 1-stage cp.async.
// smem: K[2][64][144] + V[64][72] + P[64][68] = 109568 B -> 2 CTAs/SM.
// ============================================================
#define KSTW 144
#define KSTG (64*KSTW)              // 9216 words per K stage
#define AVOFF (2*KSTG)              // 18432
#define APOFF (AVOFF + 64*72)       // 23040
#define ATT_SMEM ((APOFF + 64*68)*4)  // 109568 B

__global__ __launch_bounds__(128, 2) void attn_tc() {
    extern __shared__ float sm[];
    uint32_t sbase = smem_u32(sm);
    float* vv = sm + AVOFF;
    float* pp = sm + APOFF;

    int qt = gridDim.x - 1 - blockIdx.x;   // heavy tiles first
    int bh = blockIdx.y;
    int tid = threadIdx.x;
    int wid = tid >> 5, lane = tid & 31;
    int g = lane >> 2, tg = lane & 3;
    int rowb = wid * 16;

    const float* Kg = g_khl + (size_t)bh * L_ * 128;
    const float* Vg = g_v   + (size_t)bh * L_ * DH;

    // ---- Q fragments (hi/lo) straight from global ----
    uint32_t qh[8][4], ql[8][4];
    {
        const float* Qg = g_qhl + ((size_t)bh * L_ + qt * 64) * 128;
#pragma unroll
        for (int c = 0; c < 8; c++) {
            float2 t0 = *(const float2*)(Qg + (rowb + g) * 128 + (c * 8 + tg) * 2);
            float2 t1 = *(const float2*)(Qg + (rowb + 8 + g) * 128 + (c * 8 + tg) * 2);
            float2 t2 = *(const float2*)(Qg + (rowb + g) * 128 + (c * 8 + tg + 4) * 2);
            float2 t3 = *(const float2*)(Qg + (rowb + 8 + g) * 128 + (c * 8 + tg + 4) * 2);
            qh[c][0] = __float_as_uint(t0.x); ql[c][0] = __float_as_uint(t0.y);
            qh[c][1] = __float_as_uint(t1.x); ql[c][1] = __float_as_uint(t1.y);
            qh[c][2] = __float_as_uint(t2.x); ql[c][2] = __float_as_uint(t2.y);
            qh[c][3] = __float_as_uint(t3.x); ql[c][3] = __float_as_uint(t3.y);
        }
    }

#define KISSUE(j_) do { \
        const float* Kb_ = Kg + (size_t)(j_) * 64 * 128; \
        uint32_t kd_ = sbase + (uint32_t)(((j_) & 1) * KSTG) * 4u; \
        _Pragma("unroll") \
        for (int it = 0; it < 16; it++) { \
            int lin = it * 128 + tid; \
            int r_ = lin >> 5, ch_ = lin & 31; \
            CPA16(kd_ + (uint32_t)(r_ * KSTW * 4 + ch_ * 16), Kb_ + r_ * 128 + ch_ * 4); \
        } \
        CPCOMMIT(); \
    } while (0)
#define VISSUE(j_) do { \
        const float* Vb_ = Vg + (size_t)(j_) * 64 * DH; \
        _Pragma("unroll") \
        for (int it = 0; it < 8; it++) { \
            int lin = it * 128 + tid; \
            int r_ = lin >> 4, ch_ = lin & 15; \
            CPA16(sbase + (uint32_t)((AVOFF + r_ * 72) * 4 + ch_ * 16), Vb_ + r_ * 64 + ch_ * 4); \
        } \
        CPCOMMIT(); \
    } while (0)

    float o[8][4];
#pragma unroll
    for (int nt = 0; nt < 8; nt++)
#pragma unroll
        for (int q = 0; q < 4; q++) o[nt][q] = 0.0f;
    float mr0 = -1e30f, mr1 = -1e30f, lw0 = 0.0f, lw1 = 0.0f;

    KISSUE(0); VISSUE(0); KISSUE(1);   // tile 1 always exists (32 tiles/bh)

    for (int jt = 0; jt <= qt; jt++) {
        asm volatile("cp.async.wait_group 1;" ::: "memory");
        __syncthreads();
        const float* kbs = sm + (jt & 1) * KSTG;

        // ---- S = Q K^T (3xTF32) ----
        float s[8][4];
#pragma unroll
        for (int nt = 0; nt < 8; nt++)
#pragma unroll
            for (int q = 0; q < 4; q++) s[nt][q] = 0.0f;

#pragma unroll
        for (int c = 0; c < 8; c++) {
#pragma unroll
            for (int nt = 0; nt < 8; nt++) {
                float4 bq = *(const float4*)(kbs + (nt * 8 + g) * KSTW + c * 16 + tg * 4);
                uint32_t bhv[2] = {__float_as_uint(bq.x), __float_as_uint(bq.z)};
                uint32_t blv[2] = {__float_as_uint(bq.y), __float_as_uint(bq.w)};
                mma_tf32(s[nt], qh[c], bhv);
                mma_tf32(s[nt], ql[c], bhv);
                mma_tf32(s[nt], qh[c], blv);
            }
        }

        if (jt == qt) {
            int r0 = rowb + g, r1 = rowb + 8 + g;
#pragma unroll
            for (int nt = 0; nt < 8; nt++) {
                int c0 = nt * 8 + 2 * tg;
                if (c0     > r0) s[nt][0] = -1e30f;
                if (c0 + 1 > r0) s[nt][1] = -1e30f;
                if (c0     > r1) s[nt][2] = -1e30f;
                if (c0 + 1 > r1) s[nt][3] = -1e30f;
            }
        }

        // ---- online softmax ----
        float mx0 = -1e30f, mx1 = -1e30f;
#pragma unroll
        for (int nt = 0; nt < 8; nt++) {
            mx0 = fmaxf(mx0, fmaxf(s[nt][0], s[nt][1]));
            mx1 = fmaxf(mx1, fmaxf(s[nt][2], s[nt][3]));
        }
        mx0 = fmaxf(mx0, __shfl_xor_sync(0xffffffffu, mx0, 1));
        mx0 = fmaxf(mx0, __shfl_xor_sync(0xffffffffu, mx0, 2));
        mx1 = fmaxf(mx1, __shfl_xor_sync(0xffffffffu, mx1, 1));
        mx1 = fmaxf(mx1, __shfl_xor_sync(0xffffffffu, mx1, 2));
        float mn0 = fmaxf(mr0, mx0), mn1 = fmaxf(mr1, mx1);
        float cr0 = __expf(mr0 - mn0), cr1 = __expf(mr1 - mn1);
        float sum0 = 0.0f, sum1 = 0.0f;
#pragma unroll
        for (int nt = 0; nt < 8; nt++) {
            s[nt][0] = __expf(s[nt][0] - mn0);
            s[nt][1] = __expf(s[nt][1] - mn0);
            s[nt][2] = __expf(s[nt][2] - mn1);
            s[nt][3] = __expf(s[nt][3] - mn1);
            sum0 += s[nt][0] + s[nt][1];
            sum1 += s[nt][2] + s[nt][3];
        }
        sum0 += __shfl_xor_sync(0xffffffffu, sum0, 1);
        sum0 += __shfl_xor_sync(0xffffffffu, sum0, 2);
        sum1 += __shfl_xor_sync(0xffffffffu, sum1, 1);
        sum1 += __shfl_xor_sync(0xffffffffu, sum1, 2);
        lw0 = lw0 * cr0 + sum0;
        lw1 = lw1 * cr1 + sum1;
        mr0 = mn0; mr1 = mn1;
#pragma unroll
        for (int nt = 0; nt < 8; nt++) {
            o[nt][0] *= cr0; o[nt][1] *= cr0;
            o[nt][2] *= cr1; o[nt][3] *= cr1;
        }

        // ---- P (tf32) to per-warp-private smem ----
#pragma unroll
        for (int nt = 0; nt < 8; nt++) {
            int c0 = nt * 8 + 2 * tg;
            *(float2*)(pp + (rowb + g) * 68 + c0) =
                make_float2(tfv(s[nt][0]), tfv(s[nt][1]));
            *(float2*)(pp + (rowb + 8 + g) * 68 + c0) =
                make_float2(tfv(s[nt][2]), tfv(s[nt][3]));
        }
        __syncwarp();

        // ---- O += P V ----
#pragma unroll
        for (int kk = 0; kk < 64; kk += 8) {
            uint32_t af[4];
            af[0] = __float_as_uint(pp[(rowb + g) * 68 + kk + tg]);
            af[1] = __float_as_uint(pp[(rowb + 8 + g) * 68 + kk + tg]);
            af[2] = __float_as_uint(pp[(rowb + g) * 68 + kk + tg + 4]);
            af[3] = __float_as_uint(pp[(rowb + 8 + g) * 68 + kk + tg + 4]);
#pragma unroll
            for (int nt = 0; nt < 8; nt++) {
                uint32_t bf[2] = {
                    __float_as_uint(vv[(kk + tg) * 72 + nt * 8 + g]),
                    __float_as_uint(vv[(kk + tg + 4) * 72 + nt * 8 + g])};
                mma_tf32(o[nt], af, bf);
            }
        }

        __syncthreads();   // all reads of K(jt)/V(jt) done before overwrites
        if (jt + 1 <= qt) VISSUE(jt + 1); else CPCOMMIT();
        if (jt + 2 <= qt) KISSUE(jt + 2); else CPCOMMIT();
    }

    // epilogue (tf32-rounded -> feeds out-proj GEMM)
    float i0 = 1.0f / lw0, i1 = 1.0f / lw1;
    int b = bh >> 4, h = bh & 15;
    int r0 = qt * 64 + rowb + g, r1 = r0 + 8;
#pragma unroll
    for (int nt = 0; nt < 8; nt++) {
        int col = h * DH + nt * 8 + 2 * tg;
        *(float2*)(g_ao + (size_t)(b * L_ + r0) * D_ + col) =
            make_float2(tfv(o[nt][0] * i0), tfv(o[nt][1] * i0));
        *(float2*)(g_ao + (size_t)(b * L_ + r1) * D_ + col) =
            make_float2(tfv(o[nt][2] * i1), tfv(o[nt][3] * i1));
    }
#undef KISSUE
#undef VISSUE
}

// ============================================================
extern "C" void kernel_launch(void* const* d_in, const int* in_sizes, int n_in,
                              void* d_out, int out_size) {
    const float* x    = (const float*)d_in[0];
    const float* Wqkv = (const float*)d_in[1];
    const float* Wout = (const float*)d_in[2];
    const int*   pos  = (const int*)d_in[3];
    float* out = (float*)d_out;

    float *p_qkv, *p_ao, *p_xc, *p_wq, *p_wo;
    cudaGetSymbolAddress((void**)&p_qkv, g_qkv);
    cudaGetSymbolAddress((void**)&p_ao, g_ao);
    cudaGetSymbolAddress((void**)&p_xc, g_xc);
    cudaGetSymbolAddress((void**)&p_wq, g_wq);
    cudaGetSymbolAddress((void**)&p_wo, g_wo);

    cudaFuncSetAttribute(attn_tc, cudaFuncAttributeMaxDynamicSharedMemorySize, ATT_SMEM);
    cudaFuncSetAttribute(gemm_ca, cudaFuncAttributeMaxDynamicSharedMemorySize, GEMM_SMEM);

    // 0) pre-convert operands to tf32
    conv_tf32<<<(BL * D_ / 4 + 255) / 256, 256>>>((const float4*)x, (float4*)p_xc, BL * D_ / 4);
    conv_tf32<<<(E3 * D_ / 4 + 255) / 256, 256>>>((const float4*)Wqkv, (float4*)p_wq, E3 * D_ / 4);
    conv_tf32<<<(D_ * D_ / 4 + 255) / 256, 256>>>((const float4*)Wout, (float4*)p_wo, D_ * D_ / 4);

    // 1) qkv = x @ W_qkv^T
    gemm_ca<<<dim3(E3 / 256, BL / 128), 256, GEMM_SMEM>>>(p_xc, p_wq, p_qkv, E3, D_);
    // 2) rope + split -> qhl/khl (hi/lo) + v (tf32)
    rope_split<<<(BL * E3 / 2) / 256, 256>>>(pos);
    // 3) tensor-core causal flash attention -> g_ao (tf32)
    attn_tc<<<dim3(L_ / 64, B_ * H_), 128, ATT_SMEM>>>();
    // 4) out = g_ao @ W_out^T
    gemm_ca<<<dim3(D_ / 256, BL / 128), 256, GEMM_SMEM>>>(p_ao, p_wo, out, D_, D_);
}

// round 16
// speedup vs baseline: 3.9289x; 1.2228x over previous
#include <cuda_runtime.h>
#include <cuda_bf16.h>
#include <math.h>
#include <float.h>
#include <cstdint>

#define B_  2
#define L_  2048
#define D_  1024
#define H_  16
#define DH  64
#define BL  (B_*L_)     // 4096
#define E3  (3*D_)      // 3072

// ---- scratch (static device globals; no allocation allowed) ----
__device__ float    g_qkv[(size_t)BL * E3];      // raw qkv (fp32)
__device__ uint32_t g_qhl[(size_t)B_*H_*L_*64];  // Q bf16 hi/lo packed, pre-scaled (16 MB)
__device__ uint32_t g_khl[(size_t)B_*H_*L_*64];  // K bf16 hi/lo packed              (16 MB)
__device__ float    g_v[(size_t)B_*H_*L_*DH];    // V tf32-rounded
__device__ float    g_ao[(size_t)BL * D_];       // attention out, tf32-rounded
__device__ float    g_xc[(size_t)BL * D_];       // x    tf32-rounded
__device__ float    g_wq[(size_t)E3 * D_];       // Wqkv tf32-rounded
__device__ float    g_wo[(size_t)D_ * D_];       // Wout tf32-rounded

__device__ __forceinline__ uint32_t f2tf32(float x) {
    uint32_t r;
    asm("cvt.rna.tf32.f32 %0, %1;" : "=r"(r) : "f"(x));
    return r;
}
__device__ __forceinline__ float tfv(float x) { return __uint_as_float(f2tf32(x)); }

__device__ __forceinline__ uint32_t smem_u32(const void* p) {
    uint32_t a;
    asm("{ .reg .u64 t; cvta.to.shared.u64 t, %1; cvt.u32.u64 %0, t; }" : "=r"(a) : "l"(p));
    return a;
}

__device__ __forceinline__ void mma_tf32(float* d, const uint32_t* a, const uint32_t* b) {
    asm volatile(
        "mma.sync.aligned.m16n8k8.row.col.f32.tf32.tf32.f32 "
        "{%0,%1,%2,%3}, {%4,%5,%6,%7}, {%8,%9}, {%0,%1,%2,%3};"
        : "+f"(d[0]), "+f"(d[1]), "+f"(d[2]), "+f"(d[3])
        : "r"(a[0]), "r"(a[1]), "r"(a[2]), "r"(a[3]), "r"(b[0]), "r"(b[1]));
}

__device__ __forceinline__ void mma_bf16(float* d, const uint32_t* a, const uint32_t* b) {
    asm volatile(
        "mma.sync.aligned.m16n8k16.row.col.f32.bf16.bf16.f32 "
        "{%0,%1,%2,%3}, {%4,%5,%6,%7}, {%8,%9}, {%0,%1,%2,%3};"
        : "+f"(d[0]), "+f"(d[1]), "+f"(d[2]), "+f"(d[3])
        : "r"(a[0]), "r"(a[1]), "r"(a[2]), "r"(a[3]), "r"(b[0]), "r"(b[1]));
}

// pack {lo_elem -> bits[0:16), hi_elem -> bits[16:32)}
__device__ __forceinline__ uint32_t packbf(float e_lo, float e_hi) {
    uint32_t r;
    asm("cvt.rn.bf16x2.f32 %0, %1, %2;" : "=r"(r) : "f"(e_hi), "f"(e_lo));
    return r;
}
__device__ __forceinline__ float bfv(float x) {
    return __bfloat162float(__float2bfloat16_rn(x));
}

#define LDSM4(rr, addr) \
    asm volatile("ldmatrix.sync.aligned.m8n8.x4.shared.b16 {%0,%1,%2,%3}, [%4];" \
        : "=r"((rr)[0]), "=r"((rr)[1]), "=r"((rr)[2]), "=r"((rr)[3]) : "r"(addr))

#define CPA16(dst, src) \
    asm volatile("cp.async.ca.shared.global [%0], [%1], 16;" :: "r"(dst), "l"(src))
#define CPCOMMIT() asm volatile("cp.async.commit_group;")

// ============================================================
// tf32 pre-conversion
// ============================================================
__global__ __launch_bounds__(256) void conv_tf32(const float4* __restrict__ src,
                                                 float4* __restrict__ dst, int n4) {
    int i = blockIdx.x * blockDim.x + threadIdx.x;
    if (i < n4) {
        float4 v = src[i];
        dst[i] = make_float4(tfv(v.x), tfv(v.y), tfv(v.z), tfv(v.w));
    }
}

// ============================================================
// cp.async pipelined tf32 GEMM (unchanged from R14)
// ============================================================
#define GKT 16
#define GAST 20
#define ASTG (128*GAST)
#define BSTG (256*GAST)
#define SBOFF (4*ASTG)
#define GEMM_SMEM ((4*ASTG + 4*BSTG)*4)   // 122880 B

__global__ __launch_bounds__(256, 1) void gemm_ca(const float* __restrict__ A,
                                                  const float* __restrict__ Bm,
                                                  float* __restrict__ C,
                                                  int N, int K) {
    extern __shared__ float gsm[];
    uint32_t sbase = smem_u32(gsm);

    int tid = threadIdx.x;
    int wid = tid >> 5, lane = tid & 31;
    int g = lane >> 2, tg = lane & 3;
    int wm = (wid & 1) * 64;
    int wn = (wid >> 1) * 64;
    int bn = blockIdx.x * 256;
    int bm = blockIdx.y * 128;
    const int NT = K / GKT;

    int rowA = tid >> 1;
    int cp2 = (tid & 1) * 2;
    const float* Ag = A  + (size_t)(bm + rowA) * K + cp2 * 4;
    const float* Bg = Bm + (size_t)(bn + tid) * K;
    uint32_t sa0 = sbase + (uint32_t)(rowA * GAST + cp2 * 4) * 4u;
    uint32_t sb0 = sbase + (uint32_t)(SBOFF + tid * GAST) * 4u;

    int lm = lane >> 3, lr8 = lane & 7;
    uint32_t a_lm = sbase + (uint32_t)(((wm + lr8 + (lm & 1) * 8) * GAST + (lm >> 1) * 4) * 4);
    uint32_t b_lm = sbase + (uint32_t)((SBOFF + (wn + lr8 + (lm >> 1) * 8) * GAST + (lm & 1) * 4) * 4);

#define ISSUE(kt_) do { \
        uint32_t sa_ = (uint32_t)((kt_) & 3) * (ASTG * 4u); \
        uint32_t sb_ = (uint32_t)((kt_) & 3) * (BSTG * 4u); \
        const float* ga_ = Ag + (kt_) * GKT; \
        const float* gb_ = Bg + (kt_) * GKT; \
        CPA16(sa0 + sa_,        ga_); \
        CPA16(sa0 + sa_ + 16u,  ga_ + 4); \
        CPA16(sb0 + sb_,        gb_); \
        CPA16(sb0 + sb_ + 16u,  gb_ + 4); \
        CPA16(sb0 + sb_ + 32u,  gb_ + 8); \
        CPA16(sb0 + sb_ + 48u,  gb_ + 12); \
        CPCOMMIT(); \
    } while (0)

    float acc[4][8][4];
#pragma unroll
    for (int mt = 0; mt < 4; mt++)
#pragma unroll
        for (int nt = 0; nt < 8; nt++)
#pragma unroll
            for (int q = 0; q < 4; q++) acc[mt][nt][q] = 0.0f;

    ISSUE(0); ISSUE(1); ISSUE(2);

    for (int kt = 0; kt < NT; kt++) {
        asm volatile("cp.async.wait_group 2;" ::: "memory");
        __syncthreads();
        uint32_t saoff = (uint32_t)(kt & 3) * (ASTG * 4u);
        uint32_t sboff = (uint32_t)(kt & 3) * (BSTG * 4u);
#pragma unroll
        for (int kk = 0; kk < GKT; kk += 8) {
            uint32_t af[4][4], bfm[4][4];
#pragma unroll
            for (int mt = 0; mt < 4; mt++)
                LDSM4(af[mt], a_lm + saoff + (uint32_t)((mt * 16 * GAST + kk) * 4));
#pragma unroll
            for (int p = 0; p < 4; p++)
                LDSM4(bfm[p], b_lm + sboff + (uint32_t)((p * 16 * GAST + kk) * 4));
#pragma unroll
            for (int mt = 0; mt < 4; mt++)
#pragma unroll
                for (int nt = 0; nt < 8; nt++)
                    mma_tf32(acc[mt][nt], af[mt], &bfm[nt >> 1][(nt & 1) * 2]);
        }
        if (kt + 3 < NT) ISSUE(kt + 3);
        else CPCOMMIT();
    }

#pragma unroll
    for (int mt = 0; mt < 4; mt++) {
        int rowc = bm + wm + mt * 16 + g;
#pragma unroll
        for (int nt = 0; nt < 8; nt++) {
            int col = bn + wn + nt * 8 + 2 * tg;
            *(float2*)(C + (size_t)rowc * N + col)       = make_float2(acc[mt][nt][0], acc[mt][nt][1]);
            *(float2*)(C + (size_t)(rowc + 8) * N + col) = make_float2(acc[mt][nt][2], acc[mt][nt][3]);
        }
    }
#undef ISSUE
}

// ============================================================
// RoPE + split. Q/K written as packed bf16 hi/lo, 64 words/row:
//   pair p (=elements 2p,2p+1): hi word at (p>>3)*16+(p&3)*4+((p>>2)&1)*2,
//   lo word adjacent (+1). Word = {bf16(even) low, bf16(odd) high}.
// Q pre-scaled by 1/8. V tf32-rounded plain.
// ============================================================
__global__ __launch_bounds__(256) void rope_split(const int* __restrict__ pos_ids) {
    int idx = blockIdx.x * blockDim.x + threadIdx.x;
    int i = idx & 31;                 // pair index p
    int rest = idx >> 5;
    int h = rest & 15;
    int rest2 = rest >> 4;
    int s = rest2 % 3;
    int bl = rest2 / 3;

    const float2 e = *(const float2*)(g_qkv + (size_t)bl * E3 + (s * H_ + h) * DH + 2 * i);

    int b = bl >> 11;
    int l = bl & (L_ - 1);
    size_t bh_row = (size_t)(b * H_ + h) * L_ + l;

    if (s == 2) {
        *(float2*)(g_v + bh_row * DH + 2 * i) = make_float2(tfv(e.x), tfv(e.y));
    } else {
        float pos = (float)pos_ids[bl];
        float invf = powf(10000.0f, -(float)i * (1.0f / 32.0f));
        float ang = pos * invf;
        float cs, sn;
        sincosf(ang, &sn, &cs);
        float rx = e.x * cs - e.y * sn;
        float ry = e.x * sn + e.y * cs;
        if (s == 0) { rx *= 0.125f; ry *= 0.125f; }
        float hx = bfv(rx), hy = bfv(ry);
        uint32_t hw = packbf(rx, ry);                 // rounded hi pair
        uint32_t lw = packbf(rx - hx, ry - hy);       // lo pair
        int w = (i >> 3) * 16 + (i & 3) * 4 + ((i >> 2) & 1) * 2;
        uint32_t* dst = (s == 0 ? g_qhl : g_khl) + bh_row * 64;
        *(uint2*)(dst + w) = make_uint2(hw, lw);
    }
}

// ============================================================
// Tensor-core causal flash attention.
// QK^T: 3xBF16 m16n8k16 (Q frags in regs, K 2-stage cp.async, KROW=80).
// PV: tf32 m16n8k8 (unchanged).
// smem: K[2][64][80]w + V[64][72] + P[64][68] = 76800 B -> 2 CTAs/SM.
// ============================================================
#define KROW 80
#define KSTG (64*KROW)              // 5120 words per K stage
#define AVOFF (2*KSTG)              // 10240
#define APOFF (AVOFF + 64*72)       // 14848
#define ATT_SMEM ((APOFF + 64*68)*4)  // 76800 B

__global__ __launch_bounds__(128, 2) void attn_tc() {
    extern __shared__ float sm[];
    uint32_t sbase = smem_u32(sm);
    float* vv = sm + AVOFF;
    float* pp = sm + APOFF;

    int qt = gridDim.x - 1 - blockIdx.x;   // heavy tiles first
    int bh = blockIdx.y;
    int tid = threadIdx.x;
    int wid = tid >> 5, lane = tid & 31;
    int g = lane >> 2, tg = lane & 3;
    int rowb = wid * 16;

    const uint32_t* Kg = g_khl + (size_t)bh * L_ * 64;
    const float*    Vg = g_v   + (size_t)bh * L_ * DH;

    // ---- Q bf16 hi/lo fragments straight from global ----
    uint32_t qh[4][4], ql[4][4];
    {
        const uint32_t* Qg = g_qhl + ((size_t)bh * L_ + qt * 64) * 64;
#pragma unroll
        for (int c = 0; c < 4; c++) {
            uint4 t0 = *(const uint4*)(Qg + (rowb + g) * 64 + c * 16 + tg * 4);
            uint4 t1 = *(const uint4*)(Qg + (rowb + 8 + g) * 64 + c * 16 + tg * 4);
            qh[c][0] = t0.x; ql[c][0] = t0.y;   // pair tg   (k=2tg,2tg+1), row g
            qh[c][1] = t1.x; ql[c][1] = t1.y;   // row g+8
            qh[c][2] = t0.z; ql[c][2] = t0.w;   // pair tg+4 (k+8), row g
            qh[c][3] = t1.z; ql[c][3] = t1.w;   // row g+8
        }
    }

#define KISSUE(j_) do { \
        const uint32_t* Kb_ = Kg + (size_t)(j_) * 64 * 64; \
        uint32_t kd_ = sbase + (uint32_t)(((j_) & 1) * KSTG) * 4u; \
        _Pragma("unroll") \
        for (int it = 0; it < 8; it++) { \
            int lin = it * 128 + tid; \
            int r_ = lin >> 4, ch_ = lin & 15; \
            CPA16(kd_ + (uint32_t)((r_ * KROW + ch_ * 4) * 4), Kb_ + r_ * 64 + ch_ * 4); \
        } \
        CPCOMMIT(); \
    } while (0)
#define VISSUE(j_) do { \
        const float* Vb_ = Vg + (size_t)(j_) * 64 * DH; \
        _Pragma("unroll") \
        for (int it = 0; it < 8; it++) { \
            int lin = it * 128 + tid; \
            int r_ = lin >> 4, ch_ = lin & 15; \
            CPA16(sbase + (uint32_t)((AVOFF + r_ * 72) * 4 + ch_ * 16), Vb_ + r_ * 64 + ch_ * 4); \
        } \
        CPCOMMIT(); \
    } while (0)

    float o[8][4];
#pragma unroll
    for (int nt = 0; nt < 8; nt++)
#pragma unroll
        for (int q = 0; q < 4; q++) o[nt][q] = 0.0f;
    float mr0 = -1e30f, mr1 = -1e30f, lw0 = 0.0f, lw1 = 0.0f;

    KISSUE(0); VISSUE(0); KISSUE(1);

    for (int jt = 0; jt <= qt; jt++) {
        asm volatile("cp.async.wait_group 1;" ::: "memory");
        __syncthreads();
        const uint32_t* kbs = (const uint32_t*)sm + (jt & 1) * KSTG;

        // ---- S = Q K^T (3xBF16, m16n8k16) ----
        float s[8][4];
#pragma unroll
        for (int nt = 0; nt < 8; nt++)
#pragma unroll
            for (int q = 0; q < 4; q++) s[nt][q] = 0.0f;

#pragma unroll
        for (int c = 0; c < 4; c++) {
#pragma unroll
            for (int nt = 0; nt < 8; nt++) {
                uint4 bq = *(const uint4*)(kbs + (nt * 8 + g) * KROW + c * 16 + tg * 4);
                uint32_t bhv[2] = {bq.x, bq.z};   // hi pairs (p, p+4)
                uint32_t blv[2] = {bq.y, bq.w};   // lo pairs
                mma_bf16(s[nt], qh[c], bhv);
                mma_bf16(s[nt], ql[c], bhv);
                mma_bf16(s[nt], qh[c], blv);
            }
        }

        if (jt == qt) {
            int r0 = rowb + g, r1 = rowb + 8 + g;
#pragma unroll
            for (int nt = 0; nt < 8; nt++) {
                int c0 = nt * 8 + 2 * tg;
                if (c0     > r0) s[nt][0] = -1e30f;
                if (c0 + 1 > r0) s[nt][1] = -1e30f;
                if (c0     > r1) s[nt][2] = -1e30f;
                if (c0 + 1 > r1) s[nt][3] = -1e30f;
            }
        }

        // ---- online softmax ----
        float mx0 = -1e30f, mx1 = -1e30f;
#pragma unroll
        for (int nt = 0; nt < 8; nt++) {
            mx0 = fmaxf(mx0, fmaxf(s[nt][0], s[nt][1]));
            mx1 = fmaxf(mx1, fmaxf(s[nt][2], s[nt][3]));
        }
        mx0 = fmaxf(mx0, __shfl_xor_sync(0xffffffffu, mx0, 1));
        mx0 = fmaxf(mx0, __shfl_xor_sync(0xffffffffu, mx0, 2));
        mx1 = fmaxf(mx1, __shfl_xor_sync(0xffffffffu, mx1, 1));
        mx1 = fmaxf(mx1, __shfl_xor_sync(0xffffffffu, mx1, 2));
        float mn0 = fmaxf(mr0, mx0), mn1 = fmaxf(mr1, mx1);
        float cr0 = __expf(mr0 - mn0), cr1 = __expf(mr1 - mn1);
        float sum0 = 0.0f, sum1 = 0.0f;
#pragma unroll
        for (int nt = 0; nt < 8; nt++) {
            s[nt][0] = __expf(s[nt][0] - mn0);
            s[nt][1] = __expf(s[nt][1] - mn0);
            s[nt][2] = __expf(s[nt][2] - mn1);
            s[nt][3] = __expf(s[nt][3] - mn1);
            sum0 += s[nt][0] + s[nt][1];
            sum1 += s[nt][2] + s[nt][3];
        }
        sum0 += __shfl_xor_sync(0xffffffffu, sum0, 1);
        sum0 += __shfl_xor_sync(0xffffffffu, sum0, 2);
        sum1 += __shfl_xor_sync(0xffffffffu, sum1, 1);
        sum1 += __shfl_xor_sync(0xffffffffu, sum1, 2);
        lw0 = lw0 * cr0 + sum0;
        lw1 = lw1 * cr1 + sum1;
        mr0 = mn0; mr1 = mn1;
#pragma unroll
        for (int nt = 0; nt < 8; nt++) {
            o[nt][0] *= cr0; o[nt][1] *= cr0;
            o[nt][2] *= cr1; o[nt][3] *= cr1;
        }

        // ---- P (tf32) to per-warp-private smem ----
#pragma unroll
        for (int nt = 0; nt < 8; nt++) {
            int c0 = nt * 8 + 2 * tg;
            *(float2*)(pp + (rowb + g) * 68 + c0) =
                make_float2(tfv(s[nt][0]), tfv(s[nt][1]));
            *(float2*)(pp + (rowb + 8 + g) * 68 + c0) =
                make_float2(tfv(s[nt][2]), tfv(s[nt][3]));
        }
        __syncwarp();

        // ---- O += P V (tf32) ----
#pragma unroll
        for (int kk = 0; kk < 64; kk += 8) {
            uint32_t af[4];
            af[0] = __float_as_uint(pp[(rowb + g) * 68 + kk + tg]);
            af[1] = __float_as_uint(pp[(rowb + 8 + g) * 68 + kk + tg]);
            af[2] = __float_as_uint(pp[(rowb + g) * 68 + kk + tg + 4]);
            af[3] = __float_as_uint(pp[(rowb + 8 + g) * 68 + kk + tg + 4]);
#pragma unroll
            for (int nt = 0; nt < 8; nt++) {
                uint32_t bf[2] = {
                    __float_as_uint(vv[(kk + tg) * 72 + nt * 8 + g]),
                    __float_as_uint(vv[(kk + tg + 4) * 72 + nt * 8 + g])};
                mma_tf32(o[nt], af, bf);
            }
        }

        __syncthreads();   // all reads of K(jt)/V(jt) done before overwrites
        if (jt + 1 <= qt) VISSUE(jt + 1); else CPCOMMIT();
        if (jt + 2 <= qt) KISSUE(jt + 2); else CPCOMMIT();
    }

    // epilogue (tf32-rounded -> feeds out-proj GEMM)
    float i0 = 1.0f / lw0, i1 = 1.0f / lw1;
    int b = bh >> 4, h = bh & 15;
    int r0 = qt * 64 + rowb + g, r1 = r0 + 8;
#pragma unroll
    for (int nt = 0; nt < 8; nt++) {
        int col = h * DH + nt * 8 + 2 * tg;
        *(float2*)(g_ao + (size_t)(b * L_ + r0) * D_ + col) =
            make_float2(tfv(o[nt][0] * i0), tfv(o[nt][1] * i0));
        *(float2*)(g_ao + (size_t)(b * L_ + r1) * D_ + col) =
            make_float2(tfv(o[nt][2] * i1), tfv(o[nt][3] * i1));
    }
#undef KISSUE
#undef VISSUE
}

// ============================================================
extern "C" void kernel_launch(void* const* d_in, const int* in_sizes, int n_in,
                              void* d_out, int out_size) {
    const float* x    = (const float*)d_in[0];
    const float* Wqkv = (const float*)d_in[1];
    const float* Wout = (const float*)d_in[2];
    const int*   pos  = (const int*)d_in[3];
    float* out = (float*)d_out;

    float *p_qkv, *p_ao, *p_xc, *p_wq, *p_wo;
    cudaGetSymbolAddress((void**)&p_qkv, g_qkv);
    cudaGetSymbolAddress((void**)&p_ao, g_ao);
    cudaGetSymbolAddress((void**)&p_xc, g_xc);
    cudaGetSymbolAddress((void**)&p_wq, g_wq);
    cudaGetSymbolAddress((void**)&p_wo, g_wo);

    cudaFuncSetAttribute(attn_tc, cudaFuncAttributeMaxDynamicSharedMemorySize, ATT_SMEM);
    cudaFuncSetAttribute(gemm_ca, cudaFuncAttributeMaxDynamicSharedMemorySize, GEMM_SMEM);

    // 0) pre-convert operands to tf32
    conv_tf32<<<(BL * D_ / 4 + 255) / 256, 256>>>((const float4*)x, (float4*)p_xc, BL * D_ / 4);
    conv_tf32<<<(E3 * D_ / 4 + 255) / 256, 256>>>((const float4*)Wqkv, (float4*)p_wq, E3 * D_ / 4);
    conv_tf32<<<(D_ * D_ / 4 + 255) / 256, 256>>>((const float4*)Wout, (float4*)p_wo, D_ * D_ / 4);

    // 1) qkv = x @ W_qkv^T
    gemm_ca<<<dim3(E3 / 256, BL / 128), 256, GEMM_SMEM>>>(p_xc, p_wq, p_qkv, E3, D_);
    // 2) rope + split -> qhl/khl (bf16 hi/lo) + v (tf32)
    rope_split<<<(BL * E3 / 2) / 256, 256>>>(pos);
    // 3) tensor-core causal flash attention -> g_ao (tf32)
    attn_tc<<<dim3(L_ / 64, B_ * H_), 128, ATT_SMEM>>>();
    // 4) out = g_ao @ W_out^T
    gemm_ca<<<dim3(D_ / 256, BL / 128), 256, GEMM_SMEM>>>(p_ao, p_wo, out, D_, D_);
}